// round 2
// baseline (speedup 1.0000x reference)
#include <cuda_runtime.h>
#include <cstdint>
#include <math.h>

#define U_  256
#define B_  32
#define T_  2048
#define X3  768      // 3U
#define YCH 512      // 2U
#define KP  260      // padded k-stride (bank-conflict free, 16B aligned)
#define REC_THREADS 128
#define REC_SMEM_FLOATS (96*KP + 2*4*KP)
#define REC_SMEM_BYTES  (REC_SMEM_FLOATS*4)

// Scratch: input projections per direction + inter-layer hidden states
__device__ float g_xp[2][B_*T_*X3];   // [dir][(b*T+t)*768 + c]
__device__ float g_h[2][B_][U_];      // final hidden state handoff between layers

// ---------------------------------------------------------------------------
// helpers
// ---------------------------------------------------------------------------
__device__ __forceinline__ uint32_t smem_u32(const void* p) {
    uint32_t a;
    asm("{ .reg .u64 t; cvta.to.shared.u64 t, %1; cvt.u32.u64 %0, t; }"
        : "=r"(a) : "l"(p));
    return a;
}
__device__ __forceinline__ uint32_t mapa_rank(uint32_t addr, int r) {
    uint32_t out;
    asm("mapa.shared::cluster.u32 %0, %1, %2;" : "=r"(out) : "r"(addr), "r"(r));
    return out;
}
__device__ __forceinline__ void st_cluster_f32(uint32_t addr, float v) {
    asm volatile("st.shared::cluster.f32 [%0], %1;" :: "r"(addr), "f"(v));
}
__device__ __forceinline__ uint32_t ctarank() {
    uint32_t r; asm("mov.u32 %0, %%cluster_ctarank;" : "=r"(r)); return r;
}
#define CLUSTER_SYNC_() do { \
    asm volatile("barrier.cluster.arrive.aligned;" ::: "memory"); \
    asm volatile("barrier.cluster.wait.aligned;"   ::: "memory"); \
} while (0)

// ---------------------------------------------------------------------------
// Layer 0 input projection: xp = x * Wk[0,:] + b[0,:]  (in_dim = 1)
// ---------------------------------------------------------------------------
__global__ void layer0_xp_kernel(const float* __restrict__ x,
                                 const float* __restrict__ fwk,
                                 const float* __restrict__ fwb,
                                 const float* __restrict__ bwk,
                                 const float* __restrict__ bwb)
{
    int i4 = blockIdx.x * blockDim.x + threadIdx.x;
    const int tot4 = B_*T_*X3/4;
    if (i4 >= tot4) return;
    int e  = i4 * 4;
    int c  = e % X3;
    int bt = e / X3;
    float xv = __ldg(&x[bt]);
    float4 kf = *(const float4*)&fwk[c];
    float4 bf = *(const float4*)&fwb[c];
    float4 kb = *(const float4*)&bwk[c];
    float4 bb = *(const float4*)&bwb[c];
    float4 of, ob;
    of.x = xv*kf.x + bf.x; of.y = xv*kf.y + bf.y;
    of.z = xv*kf.z + bf.z; of.w = xv*kf.w + bf.w;
    ob.x = xv*kb.x + bb.x; ob.y = xv*kb.y + bb.y;
    ob.z = xv*kb.z + bb.z; ob.w = xv*kb.w + bb.w;
    *(float4*)&g_xp[0][e] = of;
    *(float4*)&g_xp[1][e] = ob;
}

// ---------------------------------------------------------------------------
// Layers 1/2 input projection GEMM: XP[dir] = Y(65536x512) @ Wk(512x768) + b0
// 128x128x8 tile, 256 threads, 8x8 microtile.
// ---------------------------------------------------------------------------
__global__ void __launch_bounds__(256, 1) gemm_xp_kernel(
    const float* __restrict__ Yin,
    const float* __restrict__ kfw, const float* __restrict__ bfw,
    const float* __restrict__ kbw, const float* __restrict__ bbw)
{
    const int Kd = YCH, Nd = X3;
    int dir = blockIdx.z;
    const float* Wk   = dir ? kbw : kfw;
    const float* bias = dir ? bbw : bfw;     // row 0 = input bias
    float* out = g_xp[dir];

    int n0 = blockIdx.x * 128;
    int m0 = blockIdx.y * 128;

    __shared__ float As[8][132];
    __shared__ float Bs[8][132];

    int tid   = threadIdx.x;
    int a_row = tid >> 1, a_k = (tid & 1) * 4;
    int b_k   = tid >> 5, b_n = (tid & 31) * 4;
    int ty = tid >> 4, tx = tid & 15;
    int row0 = ty * 8, col0 = tx * 8;

    float acc[8][8];
#pragma unroll
    for (int i = 0; i < 8; i++)
#pragma unroll
        for (int j = 0; j < 8; j++) acc[i][j] = 0.f;

    float4 ra = *(const float4*)&Yin[(size_t)(m0 + a_row)*Kd + a_k];
    float4 rb = *(const float4*)&Wk[(size_t)b_k*Nd + n0 + b_n];

    for (int kt = 0; kt < Kd/8; kt++) {
        As[a_k+0][a_row] = ra.x;
        As[a_k+1][a_row] = ra.y;
        As[a_k+2][a_row] = ra.z;
        As[a_k+3][a_row] = ra.w;
        *(float4*)&Bs[b_k][b_n] = rb;
        __syncthreads();
        if (kt + 1 < Kd/8) {
            ra = *(const float4*)&Yin[(size_t)(m0 + a_row)*Kd + (kt+1)*8 + a_k];
            rb = *(const float4*)&Wk[(size_t)((kt+1)*8 + b_k)*Nd + n0 + b_n];
        }
#pragma unroll
        for (int k = 0; k < 8; k++) {
            float4 a0 = *(const float4*)&As[k][row0];
            float4 a1 = *(const float4*)&As[k][row0+4];
            float4 b0 = *(const float4*)&Bs[k][col0];
            float4 b1 = *(const float4*)&Bs[k][col0+4];
            float av[8] = {a0.x,a0.y,a0.z,a0.w,a1.x,a1.y,a1.z,a1.w};
            float bv[8] = {b0.x,b0.y,b0.z,b0.w,b1.x,b1.y,b1.z,b1.w};
#pragma unroll
            for (int i = 0; i < 8; i++)
#pragma unroll
                for (int j = 0; j < 8; j++)
                    acc[i][j] = fmaf(av[i], bv[j], acc[i][j]);
        }
        __syncthreads();
    }

    float bcol[8];
#pragma unroll
    for (int j = 0; j < 8; j++) bcol[j] = __ldg(&bias[n0 + col0 + j]);

#pragma unroll
    for (int i = 0; i < 8; i++) {
        float4 o0, o1;
        o0.x = acc[i][0] + bcol[0]; o0.y = acc[i][1] + bcol[1];
        o0.z = acc[i][2] + bcol[2]; o0.w = acc[i][3] + bcol[3];
        o1.x = acc[i][4] + bcol[4]; o1.y = acc[i][5] + bcol[5];
        o1.z = acc[i][6] + bcol[6]; o1.w = acc[i][7] + bcol[7];
        size_t r = (size_t)(m0 + row0 + i) * Nd + n0 + col0;
        *(float4*)&out[r]     = o0;
        *(float4*)&out[r + 4] = o1;
    }
}

// ---------------------------------------------------------------------------
// Recurrence: one kernel per layer. Grid = 128 CTAs, clusters of 8.
//   cluster = (dir, batch-group of 4 rows); rank owns 32 U-columns.
//   Per CTA SMEM: Wr slice [96 rows x 256 k] (rows: z(0..31), r(32..63), h(64..95)),
//   plus parity-double-buffered full h[4][256].
//   Each step: 3-gate dot products from SMEM, gates, push new h slice to all
//   8 ranks via st.shared::cluster, one cluster barrier.
// ---------------------------------------------------------------------------
__global__ void __cluster_dims__(8, 1, 1) __launch_bounds__(REC_THREADS, 1)
rec_kernel(const float* __restrict__ wr_fw, const float* __restrict__ bias_fw,
           const float* __restrict__ wr_bw, const float* __restrict__ bias_bw,
           float* __restrict__ y, float* __restrict__ hcat, int layer)
{
    extern __shared__ float sm[];
    float* Wsm = sm;
    float* Hsm = sm + 96*KP;

    int rank = (int)ctarank();
    int cidx = blockIdx.x >> 3;       // 0..15
    int dir  = cidx >> 3;             // 0 fw, 1 bw
    int bg   = cidx & 7;              // batch group (4 rows)
    int tid  = threadIdx.x;
    int jl   = tid >> 2;              // 0..31 local column
    int bl   = tid & 3;               // 0..3 local batch
    int jglob = rank*32 + jl;
    int bglob = bg*4 + bl;

    const float* Wr   = dir ? wr_bw   : wr_fw;
    const float* bias = dir ? bias_bw : bias_fw;
    const float* xp   = g_xp[dir];

    // Load weight slice: Wsm[(g*32+j)*KP + k] = Wr[k][g*256 + rank*32 + j]
    for (int idx = tid; idx < 96*256; idx += REC_THREADS) {
        int k   = idx / 96;
        int r96 = idx - k*96;
        int g = r96 >> 5, j = r96 & 31;
        Wsm[(g*32 + j)*KP + k] = __ldg(&Wr[k*X3 + g*256 + rank*32 + j]);
    }
    // Initial hidden state
    if (layer == 0) {
        for (int i = tid; i < 2*4*KP; i += REC_THREADS) Hsm[i] = 0.f;
    } else {
        for (int i = tid; i < 4*256; i += REC_THREADS) {
            int b = i >> 8, k = i & 255;
            Hsm[b*KP + k] = g_h[dir][bg*4 + b][k];
        }
    }
    // Recurrent biases (row 1 of bias array)
    float bz = __ldg(&bias[X3 +       jglob]);
    float br = __ldg(&bias[X3 + 256 + jglob]);
    float bh = __ldg(&bias[X3 + 512 + jglob]);
    __syncthreads();

    uint32_t hbase = smem_u32(Hsm);
    uint32_t peer[8];
#pragma unroll
    for (int r = 0; r < 8; r++) peer[r] = mapa_rank(hbase, r);
    uint32_t off_self = (uint32_t)((bl*KP + jglob) * 4);

    const float4* wz4 = (const float4*)(Wsm + (     jl)*KP);
    const float4* wr4 = (const float4*)(Wsm + (32 + jl)*KP);
    const float4* wh4 = (const float4*)(Wsm + (64 + jl)*KP);

    int p = 0;
    float hn = 0.f;
    for (int s = 0; s < T_; s++) {
        int tt = dir ? (T_-1-s) : s;
        size_t xrow = ((size_t)bglob*T_ + tt) * X3;
        // issue xp loads early; consumed after the ~1.5K-cycle dot loop
        float xz = __ldg(&xp[xrow +       jglob]);
        float xr = __ldg(&xp[xrow + 256 + jglob]);
        float xh = __ldg(&xp[xrow + 512 + jglob]);

        const float4* hv4 = (const float4*)(Hsm + (p*4 + bl)*KP);
        float az0 = bz, az1 = 0.f, ar0 = br, ar1 = 0.f, ah0 = bh, ah1 = 0.f;
#pragma unroll 8
        for (int k4 = 0; k4 < 64; k4++) {
            float4 h4 = hv4[k4];
            float4 w;
            w = wz4[k4];
            az0 = fmaf(h4.x, w.x, az0); az1 = fmaf(h4.y, w.y, az1);
            az0 = fmaf(h4.z, w.z, az0); az1 = fmaf(h4.w, w.w, az1);
            w = wr4[k4];
            ar0 = fmaf(h4.x, w.x, ar0); ar1 = fmaf(h4.y, w.y, ar1);
            ar0 = fmaf(h4.z, w.z, ar0); ar1 = fmaf(h4.w, w.w, ar1);
            w = wh4[k4];
            ah0 = fmaf(h4.x, w.x, ah0); ah1 = fmaf(h4.y, w.y, ah1);
            ah0 = fmaf(h4.z, w.z, ah0); ah1 = fmaf(h4.w, w.w, ah1);
        }
        float hz = az0 + az1, hr = ar0 + ar1, hh = ah0 + ah1;
        float z    = 1.f / (1.f + expf(-(xz + hz)));
        float r    = 1.f / (1.f + expf(-(xr + hr)));
        float cand = tanhf(xh + r * hh);
        float hold = Hsm[(p*4 + bl)*KP + jglob];
        hn = fmaf(z, hold - cand, cand);      // z*h + (1-z)*cand

        y[((size_t)bglob*T_ + tt)*YCH + dir*256 + jglob] = hn;

        // push to next-parity h buffer of every rank (incl. self)
        uint32_t off = off_self + (uint32_t)((p ^ 1) * 4 * KP * 4);
#pragma unroll
        for (int rr = 0; rr < 8; rr++) st_cluster_f32(peer[rr] + off, hn);

        CLUSTER_SYNC_();   // release stores, acquire for next-step reads
        p ^= 1;
    }

    if (layer == 2)
        hcat[(size_t)bglob*YCH + dir*256 + jglob] = hn;
    else
        g_h[dir][bglob][jglob] = hn;
}

// ---------------------------------------------------------------------------
// launch
// ---------------------------------------------------------------------------
extern "C" void kernel_launch(void* const* d_in, const int* in_sizes, int n_in,
                              void* d_out, int out_size)
{
    (void)in_sizes; (void)n_in; (void)out_size;
    const float* x = (const float*)d_in[0];
    const float* p[18];
    for (int i = 0; i < 18; i++) p[i] = (const float*)d_in[1 + i];
    // layer l: fwk=p[6l], fwr=p[6l+1], fwb=p[6l+2], bwk=p[6l+3], bwr=p[6l+4], bwb=p[6l+5]

    float* y    = (float*)d_out;                    // [B][T][512], inter-layer reuse
    float* hcat = y + (size_t)B_ * T_ * YCH;        // [B][512] final states

    cudaFuncSetAttribute(rec_kernel,
                         cudaFuncAttributeMaxDynamicSharedMemorySize,
                         REC_SMEM_BYTES);

    const int tot4 = B_*T_*X3/4;
    layer0_xp_kernel<<<(tot4 + 255)/256, 256>>>(x, p[0], p[2], p[3], p[5]);
    rec_kernel<<<128, REC_THREADS, REC_SMEM_BYTES>>>(p[1], p[2], p[4], p[5], y, hcat, 0);

    dim3 gg(X3/128, (B_*T_)/128, 2);
    gemm_xp_kernel<<<gg, 256>>>(y, p[6], p[8], p[9], p[11]);
    rec_kernel<<<128, REC_THREADS, REC_SMEM_BYTES>>>(p[7], p[8], p[10], p[11], y, hcat, 1);

    gemm_xp_kernel<<<gg, 256>>>(y, p[12], p[14], p[15], p[17]);
    rec_kernel<<<128, REC_THREADS, REC_SMEM_BYTES>>>(p[13], p[14], p[16], p[17], y, hcat, 2);
}

// round 3
// speedup vs baseline: 1.0927x; 1.0927x over previous
#include <cuda_runtime.h>
#include <cstdint>
#include <math.h>

#define U_  256
#define B_  32
#define T_  2048
#define X3  768      // 3U
#define YCH 512      // 2U
#define KP  260      // padded k-stride (bank-conflict free, 16B aligned)
#define REC_THREADS 256
// smem: W slice (96 rows x KP) + double-buffered h (2*4*KP) + reduction (128*4)
#define REC_SMEM_FLOATS (96*KP + 2*4*KP + 512)
#define REC_SMEM_BYTES  (REC_SMEM_FLOATS*4)

// Scratch: input projections per direction + inter-layer hidden states
__device__ float g_xp[2][B_*T_*X3];   // [dir][(b*T+t)*768 + c]
__device__ float g_h[2][B_][U_];      // final hidden state handoff between layers

// ---------------------------------------------------------------------------
// helpers
// ---------------------------------------------------------------------------
__device__ __forceinline__ uint32_t smem_u32(const void* p) {
    uint32_t a;
    asm("{ .reg .u64 t; cvta.to.shared.u64 t, %1; cvt.u32.u64 %0, t; }"
        : "=r"(a) : "l"(p));
    return a;
}
__device__ __forceinline__ uint32_t mapa_rank(uint32_t addr, int r) {
    uint32_t out;
    asm("mapa.shared::cluster.u32 %0, %1, %2;" : "=r"(out) : "r"(addr), "r"(r));
    return out;
}
__device__ __forceinline__ void st_cluster_f32(uint32_t addr, float v) {
    asm volatile("st.shared::cluster.f32 [%0], %1;" :: "r"(addr), "f"(v));
}
__device__ __forceinline__ uint32_t ctarank() {
    uint32_t r; asm("mov.u32 %0, %%cluster_ctarank;" : "=r"(r)); return r;
}
#define CLUSTER_ARRIVE_() asm volatile("barrier.cluster.arrive.aligned;" ::: "memory")
#define CLUSTER_WAIT_()   asm volatile("barrier.cluster.wait.aligned;"   ::: "memory")

__device__ __forceinline__ float fast_sigmoid(float x) {
    return __fdividef(1.f, 1.f + __expf(-x));
}
__device__ __forceinline__ float fast_tanh(float x) {
    float e = __expf(-2.f * x);
    return __fdividef(1.f - e, 1.f + e);
}

// ---------------------------------------------------------------------------
// Layer 0 input projection: xp = x * Wk[0,:] + b[0,:]  (in_dim = 1)
// ---------------------------------------------------------------------------
__global__ void layer0_xp_kernel(const float* __restrict__ x,
                                 const float* __restrict__ fwk,
                                 const float* __restrict__ fwb,
                                 const float* __restrict__ bwk,
                                 const float* __restrict__ bwb)
{
    int i4 = blockIdx.x * blockDim.x + threadIdx.x;
    const int tot4 = B_*T_*X3/4;
    if (i4 >= tot4) return;
    int e  = i4 * 4;
    int c  = e % X3;
    int bt = e / X3;
    float xv = __ldg(&x[bt]);
    float4 kf = *(const float4*)&fwk[c];
    float4 bf = *(const float4*)&fwb[c];
    float4 kb = *(const float4*)&bwk[c];
    float4 bb = *(const float4*)&bwb[c];
    float4 of, ob;
    of.x = xv*kf.x + bf.x; of.y = xv*kf.y + bf.y;
    of.z = xv*kf.z + bf.z; of.w = xv*kf.w + bf.w;
    ob.x = xv*kb.x + bb.x; ob.y = xv*kb.y + bb.y;
    ob.z = xv*kb.z + bb.z; ob.w = xv*kb.w + bb.w;
    *(float4*)&g_xp[0][e] = of;
    *(float4*)&g_xp[1][e] = ob;
}

// ---------------------------------------------------------------------------
// Layers 1/2 input projection GEMM: XP[dir] = Y(65536x512) @ Wk(512x768) + b0
// 128x128x8 tile, 256 threads, 8x8 microtile, ping-pong double-buffered smem.
// ---------------------------------------------------------------------------
__global__ void __launch_bounds__(256) gemm_xp_kernel(
    const float* __restrict__ Yin,
    const float* __restrict__ kfw, const float* __restrict__ bfw,
    const float* __restrict__ kbw, const float* __restrict__ bbw)
{
    const int Kd = YCH, Nd = X3;
    int dir = blockIdx.z;
    const float* Wk   = dir ? kbw : kfw;
    const float* bias = dir ? bbw : bfw;     // row 0 = input bias
    float* out = g_xp[dir];

    int n0 = blockIdx.x * 128;
    int m0 = blockIdx.y * 128;

    __shared__ float As[2][8][132];
    __shared__ float Bs[2][8][132];

    int tid   = threadIdx.x;
    int a_row = tid >> 1, a_k = (tid & 1) * 4;
    int b_k   = tid >> 5, b_n = (tid & 31) * 4;
    int ty = tid >> 4, tx = tid & 15;
    int row0 = ty * 8, col0 = tx * 8;

    float acc[8][8];
#pragma unroll
    for (int i = 0; i < 8; i++)
#pragma unroll
        for (int j = 0; j < 8; j++) acc[i][j] = 0.f;

    const int NT = Kd / 8;   // 64 k-tiles

    float4 ra = *(const float4*)&Yin[(size_t)(m0 + a_row)*Kd + a_k];
    float4 rb = *(const float4*)&Wk[(size_t)b_k*Nd + n0 + b_n];
    As[0][a_k+0][a_row] = ra.x;
    As[0][a_k+1][a_row] = ra.y;
    As[0][a_k+2][a_row] = ra.z;
    As[0][a_k+3][a_row] = ra.w;
    *(float4*)&Bs[0][b_k][b_n] = rb;
    __syncthreads();

    for (int kt = 0; kt < NT; kt++) {
        int cur = kt & 1;
        if (kt + 1 < NT) {
            ra = *(const float4*)&Yin[(size_t)(m0 + a_row)*Kd + (kt+1)*8 + a_k];
            rb = *(const float4*)&Wk[(size_t)((kt+1)*8 + b_k)*Nd + n0 + b_n];
        }
#pragma unroll
        for (int k = 0; k < 8; k++) {
            float4 a0 = *(const float4*)&As[cur][k][row0];
            float4 a1 = *(const float4*)&As[cur][k][row0+4];
            float4 b0 = *(const float4*)&Bs[cur][k][col0];
            float4 b1 = *(const float4*)&Bs[cur][k][col0+4];
            float av[8] = {a0.x,a0.y,a0.z,a0.w,a1.x,a1.y,a1.z,a1.w};
            float bv[8] = {b0.x,b0.y,b0.z,b0.w,b1.x,b1.y,b1.z,b1.w};
#pragma unroll
            for (int i = 0; i < 8; i++)
#pragma unroll
                for (int j = 0; j < 8; j++)
                    acc[i][j] = fmaf(av[i], bv[j], acc[i][j]);
        }
        if (kt + 1 < NT) {
            int nxt = cur ^ 1;
            As[nxt][a_k+0][a_row] = ra.x;
            As[nxt][a_k+1][a_row] = ra.y;
            As[nxt][a_k+2][a_row] = ra.z;
            As[nxt][a_k+3][a_row] = ra.w;
            *(float4*)&Bs[nxt][b_k][b_n] = rb;
        }
        __syncthreads();
    }

    float bcol[8];
#pragma unroll
    for (int j = 0; j < 8; j++) bcol[j] = __ldg(&bias[n0 + col0 + j]);

#pragma unroll
    for (int i = 0; i < 8; i++) {
        float4 o0, o1;
        o0.x = acc[i][0] + bcol[0]; o0.y = acc[i][1] + bcol[1];
        o0.z = acc[i][2] + bcol[2]; o0.w = acc[i][3] + bcol[3];
        o1.x = acc[i][4] + bcol[4]; o1.y = acc[i][5] + bcol[5];
        o1.z = acc[i][6] + bcol[6]; o1.w = acc[i][7] + bcol[7];
        size_t r = (size_t)(m0 + row0 + i) * Nd + n0 + col0;
        *(float4*)&out[r]     = o0;
        *(float4*)&out[r + 4] = o1;
    }
}

// ---------------------------------------------------------------------------
// Recurrence. Grid = 128 CTAs, clusters of 8, 256 threads.
//   cluster = (dir, batch-group of 4 rows); rank owns 32 U-columns.
//   k-SPLIT: warps 0-3 (kh=0) handle k 0..127, warps 4-7 (kh=1) k 128..255,
//   so each SMSP has 2 interleaving warps. kh=1 partials reduced via smem.
// ---------------------------------------------------------------------------
__global__ void __cluster_dims__(8, 1, 1) __launch_bounds__(REC_THREADS, 1)
rec_kernel(const float* __restrict__ wr_fw, const float* __restrict__ bias_fw,
           const float* __restrict__ wr_bw, const float* __restrict__ bias_bw,
           float* __restrict__ y, float* __restrict__ hcat, int layer)
{
    extern __shared__ float sm[];
    float* Wsm = sm;                 // [96][KP]
    float* Hsm = sm + 96*KP;         // [2][4][KP]
    float* Red = Hsm + 8*KP;         // [128][4]

    int rank = (int)ctarank();
    int cidx = blockIdx.x >> 3;       // 0..15
    int dir  = cidx >> 3;             // 0 fw, 1 bw
    int bg   = cidx & 7;              // batch group (4 rows)
    int tid  = threadIdx.x;
    int kh   = tid >> 7;              // k-half (warp groups 0-3 / 4-7)
    int tl   = tid & 127;
    int jl   = tl >> 2;               // 0..31 local column
    int bl   = tl & 3;                // 0..3 local batch
    int jglob = rank*32 + jl;
    int bglob = bg*4 + bl;

    const float* Wr   = dir ? wr_bw   : wr_fw;
    const float* bias = dir ? bias_bw : bias_fw;
    const float* xp   = g_xp[dir];

    // Load weight slice: Wsm[(g*32+j)*KP + k] = Wr[k][g*256 + rank*32 + j]
    for (int idx = tid; idx < 96*256; idx += REC_THREADS) {
        int k   = idx / 96;
        int r96 = idx - k*96;
        int g = r96 >> 5, j = r96 & 31;
        Wsm[(g*32 + j)*KP + k] = __ldg(&Wr[k*X3 + g*256 + rank*32 + j]);
    }
    // Initial hidden state
    if (layer == 0) {
        for (int i = tid; i < 2*4*KP; i += REC_THREADS) Hsm[i] = 0.f;
    } else {
        for (int i = tid; i < 4*256; i += REC_THREADS) {
            int b = i >> 8, k = i & 255;
            Hsm[b*KP + k] = g_h[dir][bg*4 + b][k];
        }
    }
    // Recurrent biases (row 1 of bias array) — only needed by kh=0
    float bz = 0.f, br = 0.f, bh = 0.f;
    if (kh == 0) {
        bz = __ldg(&bias[X3 +       jglob]);
        br = __ldg(&bias[X3 + 256 + jglob]);
        bh = __ldg(&bias[X3 + 512 + jglob]);
    }
    __syncthreads();

    uint32_t hbase = smem_u32(Hsm);
    uint32_t peer[8];
#pragma unroll
    for (int r = 0; r < 8; r++) peer[r] = mapa_rank(hbase, r);
    uint32_t off_self = (uint32_t)((bl*KP + jglob) * 4);

    const float4* wz4 = (const float4*)(Wsm + (     jl)*KP) + kh*32;
    const float4* wr4 = (const float4*)(Wsm + (32 + jl)*KP) + kh*32;
    const float4* wh4 = (const float4*)(Wsm + (64 + jl)*KP) + kh*32;

    int p = 0;
    float hn = 0.f;
    for (int s = 0; s < T_; s++) {
        int tt = dir ? (T_-1-s) : s;
        float xz = 0.f, xr = 0.f, xh = 0.f;
        size_t xrow = ((size_t)bglob*T_ + tt) * X3;
        if (kh == 0) {  // issue global loads early; consumed after dot loop
            xz = __ldg(&xp[xrow +       jglob]);
            xr = __ldg(&xp[xrow + 256 + jglob]);
            xh = __ldg(&xp[xrow + 512 + jglob]);
        }

        const float4* hv4 = (const float4*)(Hsm + (p*4 + bl)*KP) + kh*32;
        float az0 = 0.f, az1 = 0.f, ar0 = 0.f, ar1 = 0.f, ah0 = 0.f, ah1 = 0.f;
#pragma unroll 4
        for (int k4 = 0; k4 < 32; k4++) {
            float4 h4 = hv4[k4];
            float4 w;
            w = wz4[k4];
            az0 = fmaf(h4.x, w.x, az0); az1 = fmaf(h4.y, w.y, az1);
            az0 = fmaf(h4.z, w.z, az0); az1 = fmaf(h4.w, w.w, az1);
            w = wr4[k4];
            ar0 = fmaf(h4.x, w.x, ar0); ar1 = fmaf(h4.y, w.y, ar1);
            ar0 = fmaf(h4.z, w.z, ar0); ar1 = fmaf(h4.w, w.w, ar1);
            w = wh4[k4];
            ah0 = fmaf(h4.x, w.x, ah0); ah1 = fmaf(h4.y, w.y, ah1);
            ah0 = fmaf(h4.z, w.z, ah0); ah1 = fmaf(h4.w, w.w, ah1);
        }
        float pz = az0 + az1, pr = ar0 + ar1, ph = ah0 + ah1;

        if (kh) {
            float4 v; v.x = pz; v.y = pr; v.z = ph; v.w = 0.f;
            *(float4*)&Red[tl*4] = v;
        }
        __syncthreads();

        if (!kh) {
            float4 v = *(const float4*)&Red[tl*4];
            float hz = pz + v.x + bz;
            float hr = pr + v.y + br;
            float hh = ph + v.z + bh;
            float z    = fast_sigmoid(xz + hz);
            float r    = fast_sigmoid(xr + hr);
            float cand = fast_tanh(xh + r * hh);
            float hold = Hsm[(p*4 + bl)*KP + jglob];
            hn = fmaf(z, hold - cand, cand);      // z*h + (1-z)*cand

            // push to next-parity h buffer of every rank (incl. self)
            uint32_t off = off_self + (uint32_t)((p ^ 1) * 4 * KP * 4);
#pragma unroll
            for (int rr = 0; rr < 8; rr++) st_cluster_f32(peer[rr] + off, hn);
        }

        CLUSTER_ARRIVE_();   // release: pushes visible to whole cluster at wait
        if (!kh)
            y[((size_t)bglob*T_ + tt)*YCH + dir*256 + jglob] = hn;
        CLUSTER_WAIT_();
        p ^= 1;
    }

    if (kh == 0) {
        if (layer == 2)
            hcat[(size_t)bglob*YCH + dir*256 + jglob] = hn;
        else
            g_h[dir][bglob][jglob] = hn;
    }
}

// ---------------------------------------------------------------------------
// launch
// ---------------------------------------------------------------------------
extern "C" void kernel_launch(void* const* d_in, const int* in_sizes, int n_in,
                              void* d_out, int out_size)
{
    (void)in_sizes; (void)n_in; (void)out_size;
    const float* x = (const float*)d_in[0];
    const float* p[18];
    for (int i = 0; i < 18; i++) p[i] = (const float*)d_in[1 + i];
    // layer l: fwk=p[6l], fwr=p[6l+1], fwb=p[6l+2], bwk=p[6l+3], bwr=p[6l+4], bwb=p[6l+5]

    float* y    = (float*)d_out;                    // [B][T][512], inter-layer reuse
    float* hcat = y + (size_t)B_ * T_ * YCH;        // [B][512] final states

    cudaFuncSetAttribute(rec_kernel,
                         cudaFuncAttributeMaxDynamicSharedMemorySize,
                         REC_SMEM_BYTES);

    const int tot4 = B_*T_*X3/4;
    layer0_xp_kernel<<<(tot4 + 255)/256, 256>>>(x, p[0], p[2], p[3], p[5]);
    rec_kernel<<<128, REC_THREADS, REC_SMEM_BYTES>>>(p[1], p[2], p[4], p[5], y, hcat, 0);

    dim3 gg(X3/128, (B_*T_)/128, 2);
    gemm_xp_kernel<<<gg, 256>>>(y, p[6], p[8], p[9], p[11]);
    rec_kernel<<<128, REC_THREADS, REC_SMEM_BYTES>>>(p[7], p[8], p[10], p[11], y, hcat, 1);

    gemm_xp_kernel<<<gg, 256>>>(y, p[12], p[14], p[15], p[17]);
    rec_kernel<<<128, REC_THREADS, REC_SMEM_BYTES>>>(p[13], p[14], p[16], p[17], y, hcat, 2);
}

// round 4
// speedup vs baseline: 1.6257x; 1.4877x over previous
#include <cuda_runtime.h>
#include <cstdint>
#include <math.h>

#define U_  256
#define B_  32
#define T_  2048
#define X3  768      // 3U
#define YCH 512      // 2U
#define KP  260      // padded k-stride
#define CL  4        // cluster size (ranks)
#define CPR 64       // columns per rank
#define BGR 2        // batch rows per cluster
#define REC_THREADS 512
// smem floats: mbar pad(4) + W(192*KP) + H(2*BGR*KP) + Red(3*128*4)
#define SM_W    4
#define SM_H    (SM_W + 192*KP)
#define SM_RED  (SM_H + 2*BGR*KP)
#define REC_SMEM_FLOATS (SM_RED + 3*128*4)
#define REC_SMEM_BYTES  (REC_SMEM_FLOATS*4)

// Scratch: input projections per direction + inter-layer hidden states
__device__ float g_xp[2][B_*T_*X3];   // [dir][(b*T+t)*768 + c]
__device__ float g_h[2][B_][U_];      // final hidden state handoff between layers

// ---------------------------------------------------------------------------
// helpers
// ---------------------------------------------------------------------------
__device__ __forceinline__ uint32_t smem_u32(const void* p) {
    uint32_t a;
    asm("{ .reg .u64 t; cvta.to.shared.u64 t, %1; cvt.u32.u64 %0, t; }"
        : "=r"(a) : "l"(p));
    return a;
}
__device__ __forceinline__ uint32_t mapa_rank(uint32_t addr, int r) {
    uint32_t out;
    asm("mapa.shared::cluster.u32 %0, %1, %2;" : "=r"(out) : "r"(addr), "r"(r));
    return out;
}
__device__ __forceinline__ void st_cluster_f32(uint32_t addr, float v) {
    asm volatile("st.shared::cluster.f32 [%0], %1;" :: "r"(addr), "f"(v));
}
__device__ __forceinline__ uint32_t ctarank() {
    uint32_t r; asm("mov.u32 %0, %%cluster_ctarank;" : "=r"(r)); return r;
}
#define CLUSTER_ARRIVE_() asm volatile("barrier.cluster.arrive.aligned;" ::: "memory")
#define CLUSTER_WAIT_()   asm volatile("barrier.cluster.wait.aligned;"   ::: "memory")

__device__ __forceinline__ void mbar_init(uint32_t addr, uint32_t cnt) {
    asm volatile("mbarrier.init.shared.b64 [%0], %1;" :: "r"(addr), "r"(cnt) : "memory");
}
__device__ __forceinline__ void mbar_arrive_cluster(uint32_t addr) {
    asm volatile("mbarrier.arrive.release.cluster.shared::cluster.b64 _, [%0];"
                 :: "r"(addr) : "memory");
}
__device__ __forceinline__ void mbar_wait_parity(uint32_t addr, uint32_t parity) {
    asm volatile(
        "{\n\t"
        ".reg .pred P;\n\t"
        "WL%=:\n\t"
        "mbarrier.try_wait.parity.acquire.cluster.shared::cta.b64 P, [%0], %1, 0x989680;\n\t"
        "@!P bra WL%=;\n\t"
        "}"
        :: "r"(addr), "r"(parity) : "memory");
}

__device__ __forceinline__ float fast_sigmoid(float x) {
    return __fdividef(1.f, 1.f + __expf(-x));
}
__device__ __forceinline__ float fast_tanh(float x) {
    float e = __expf(-2.f * x);
    return __fdividef(1.f - e, 1.f + e);
}

// ---------------------------------------------------------------------------
// Layer 0 input projection: xp = x * Wk[0,:] + b[0,:]  (in_dim = 1)
// ---------------------------------------------------------------------------
__global__ void layer0_xp_kernel(const float* __restrict__ x,
                                 const float* __restrict__ fwk,
                                 const float* __restrict__ fwb,
                                 const float* __restrict__ bwk,
                                 const float* __restrict__ bwb)
{
    int i4 = blockIdx.x * blockDim.x + threadIdx.x;
    const int tot4 = B_*T_*X3/4;
    if (i4 >= tot4) return;
    int e  = i4 * 4;
    int c  = e % X3;
    int bt = e / X3;
    float xv = __ldg(&x[bt]);
    float4 kf = *(const float4*)&fwk[c];
    float4 bf = *(const float4*)&fwb[c];
    float4 kb = *(const float4*)&bwk[c];
    float4 bb = *(const float4*)&bwb[c];
    float4 of, ob;
    of.x = xv*kf.x + bf.x; of.y = xv*kf.y + bf.y;
    of.z = xv*kf.z + bf.z; of.w = xv*kf.w + bf.w;
    ob.x = xv*kb.x + bb.x; ob.y = xv*kb.y + bb.y;
    ob.z = xv*kb.z + bb.z; ob.w = xv*kb.w + bb.w;
    *(float4*)&g_xp[0][e] = of;
    *(float4*)&g_xp[1][e] = ob;
}

// ---------------------------------------------------------------------------
// Layers 1/2 input projection GEMM: XP[dir] = Y(65536x512) @ Wk(512x768) + b0
// 128x128x8 tile, 256 threads, 8x8 microtile, ping-pong double-buffered smem.
// ---------------------------------------------------------------------------
__global__ void __launch_bounds__(256) gemm_xp_kernel(
    const float* __restrict__ Yin,
    const float* __restrict__ kfw, const float* __restrict__ bfw,
    const float* __restrict__ kbw, const float* __restrict__ bbw)
{
    const int Kd = YCH, Nd = X3;
    int dir = blockIdx.z;
    const float* Wk   = dir ? kbw : kfw;
    const float* bias = dir ? bbw : bfw;     // row 0 = input bias
    float* out = g_xp[dir];

    int n0 = blockIdx.x * 128;
    int m0 = blockIdx.y * 128;

    __shared__ float As[2][8][132];
    __shared__ float Bs[2][8][132];

    int tid   = threadIdx.x;
    int a_row = tid >> 1, a_k = (tid & 1) * 4;
    int b_k   = tid >> 5, b_n = (tid & 31) * 4;
    int ty = tid >> 4, tx = tid & 15;
    int row0 = ty * 8, col0 = tx * 8;

    float acc[8][8];
#pragma unroll
    for (int i = 0; i < 8; i++)
#pragma unroll
        for (int j = 0; j < 8; j++) acc[i][j] = 0.f;

    const int NT = Kd / 8;   // 64 k-tiles

    float4 ra = *(const float4*)&Yin[(size_t)(m0 + a_row)*Kd + a_k];
    float4 rb = *(const float4*)&Wk[(size_t)b_k*Nd + n0 + b_n];
    As[0][a_k+0][a_row] = ra.x;
    As[0][a_k+1][a_row] = ra.y;
    As[0][a_k+2][a_row] = ra.z;
    As[0][a_k+3][a_row] = ra.w;
    *(float4*)&Bs[0][b_k][b_n] = rb;
    __syncthreads();

    for (int kt = 0; kt < NT; kt++) {
        int cur = kt & 1;
        if (kt + 1 < NT) {
            ra = *(const float4*)&Yin[(size_t)(m0 + a_row)*Kd + (kt+1)*8 + a_k];
            rb = *(const float4*)&Wk[(size_t)((kt+1)*8 + b_k)*Nd + n0 + b_n];
        }
#pragma unroll
        for (int k = 0; k < 8; k++) {
            float4 a0 = *(const float4*)&As[cur][k][row0];
            float4 a1 = *(const float4*)&As[cur][k][row0+4];
            float4 b0 = *(const float4*)&Bs[cur][k][col0];
            float4 b1 = *(const float4*)&Bs[cur][k][col0+4];
            float av[8] = {a0.x,a0.y,a0.z,a0.w,a1.x,a1.y,a1.z,a1.w};
            float bv[8] = {b0.x,b0.y,b0.z,b0.w,b1.x,b1.y,b1.z,b1.w};
#pragma unroll
            for (int i = 0; i < 8; i++)
#pragma unroll
                for (int j = 0; j < 8; j++)
                    acc[i][j] = fmaf(av[i], bv[j], acc[i][j]);
        }
        if (kt + 1 < NT) {
            int nxt = cur ^ 1;
            As[nxt][a_k+0][a_row] = ra.x;
            As[nxt][a_k+1][a_row] = ra.y;
            As[nxt][a_k+2][a_row] = ra.z;
            As[nxt][a_k+3][a_row] = ra.w;
            *(float4*)&Bs[nxt][b_k][b_n] = rb;
        }
        __syncthreads();
    }

    float bcol[8];
#pragma unroll
    for (int j = 0; j < 8; j++) bcol[j] = __ldg(&bias[n0 + col0 + j]);

#pragma unroll
    for (int i = 0; i < 8; i++) {
        float4 o0, o1;
        o0.x = acc[i][0] + bcol[0]; o0.y = acc[i][1] + bcol[1];
        o0.z = acc[i][2] + bcol[2]; o0.w = acc[i][3] + bcol[3];
        o1.x = acc[i][4] + bcol[4]; o1.y = acc[i][5] + bcol[5];
        o1.z = acc[i][6] + bcol[6]; o1.w = acc[i][7] + bcol[7];
        size_t r = (size_t)(m0 + row0 + i) * Nd + n0 + col0;
        *(float4*)&out[r]     = o0;
        *(float4*)&out[r + 4] = o1;
    }
}

// ---------------------------------------------------------------------------
// Recurrence. Grid = 128 CTAs, clusters of 4, 512 threads.
//   cluster = (dir, batch-group of 2 rows); rank owns 64 U-columns.
//   Weights [192 rows x 256 k] in SMEM (~200KB). 4-way k-split (kh=tid>>7):
//   each SMSP runs 4 warps. Partials from kh=1..3 reduced through SMEM.
//   Per-step sync: push h slice to 4 ranks (st.shared::cluster), bar.sync,
//   4 remote release-arrives on peer mbarriers, local acquire try_wait.
// ---------------------------------------------------------------------------
__global__ void __cluster_dims__(CL, 1, 1) __launch_bounds__(REC_THREADS, 1)
rec_kernel(const float* __restrict__ wr_fw, const float* __restrict__ bias_fw,
           const float* __restrict__ wr_bw, const float* __restrict__ bias_bw,
           float* __restrict__ y, float* __restrict__ hcat, int layer)
{
    extern __shared__ float sm[];
    float* Wsm = sm + SM_W;          // [192][KP]
    float* Hsm = sm + SM_H;          // [2][BGR][KP]
    float* Red = sm + SM_RED;        // [3][128][4]
    uint32_t mbar = smem_u32(sm);    // 8B mbarrier at sm[0..1]

    int rank = (int)ctarank();
    int cidx = blockIdx.x >> 2;       // 0..31
    int dir  = cidx >> 4;             // 0 fw, 1 bw
    int bg   = cidx & 15;             // batch group (2 rows)
    int tid  = threadIdx.x;
    int kh   = tid >> 7;              // k-quarter 0..3
    int tl   = tid & 127;
    int jl   = tl >> 1;               // 0..63 local column
    int bl   = tl & 1;                // 0..1 local batch
    int jglob = rank*CPR + jl;
    int bglob = bg*BGR + bl;

    const float* Wr   = dir ? wr_bw   : wr_fw;
    const float* bias = dir ? bias_bw : bias_fw;
    const float* xp   = g_xp[dir];

    if (tid == 0) mbar_init(mbar, CL);

    // Load weight slice: Wsm[(g*64+j)*KP + k] = Wr[k][g*256 + rank*64 + j]
    for (int idx = tid; idx < 192*256; idx += REC_THREADS) {
        int k    = idx / 192;
        int r192 = idx - k*192;
        int g = r192 >> 6, j = r192 & 63;
        Wsm[(g*CPR + j)*KP + k] = __ldg(&Wr[k*X3 + g*256 + rank*CPR + j]);
    }
    // Initial hidden state into parity-0 buffer
    for (int i = tid; i < BGR*256; i += REC_THREADS) {
        int b = i >> 8, k = i & 255;
        Hsm[b*KP + k] = layer ? g_h[dir][bg*BGR + b][k] : 0.f;
    }
    // Recurrent biases (row 1 of bias array) — only needed by kh=0
    float bz = 0.f, br = 0.f, bh = 0.f;
    if (kh == 0) {
        bz = __ldg(&bias[X3 +       jglob]);
        br = __ldg(&bias[X3 + 256 + jglob]);
        bh = __ldg(&bias[X3 + 512 + jglob]);
    }
    __syncthreads();
    CLUSTER_ARRIVE_();   // all mbarriers initialised + H/W loaded cluster-wide
    CLUSTER_WAIT_();

    uint32_t hbase = smem_u32(Hsm);
    uint32_t peerH[CL], peerM[CL];
#pragma unroll
    for (int r = 0; r < CL; r++) {
        peerH[r] = mapa_rank(hbase, r);
        peerM[r] = mapa_rank(mbar, r);
    }
    uint32_t off_self = (uint32_t)((bl*KP + jglob) * 4);

    const float4* wz4 = (const float4*)(Wsm + (          jl)*KP) + kh*16;
    const float4* wr4 = (const float4*)(Wsm + ( CPR    + jl)*KP) + kh*16;
    const float4* wh4 = (const float4*)(Wsm + (2*CPR   + jl)*KP) + kh*16;

    // h(t-1) for this (jglob,bl) carried in-register by kh==0 threads
    float hn = (kh == 0) ? Hsm[bl*KP + jglob] : 0.f;

    // prefetch xp for step 0
    float xz = 0.f, xr = 0.f, xh = 0.f;
    if (kh == 0) {
        int tt0 = dir ? (T_-1) : 0;
        size_t xrow = ((size_t)bglob*T_ + tt0) * X3;
        xz = __ldg(&xp[xrow +       jglob]);
        xr = __ldg(&xp[xrow + 256 + jglob]);
        xh = __ldg(&xp[xrow + 512 + jglob]);
    }

    int p = 0;
    for (int s = 0; s < T_; s++) {
        int tt = dir ? (T_-1-s) : s;

        const float4* hv4 = (const float4*)(Hsm + (p*BGR + bl)*KP) + kh*16;
        float az0 = 0.f, az1 = 0.f, ar0 = 0.f, ar1 = 0.f, ah0 = 0.f, ah1 = 0.f;
#pragma unroll 4
        for (int k4 = 0; k4 < 16; k4++) {
            float4 h4 = hv4[k4];
            float4 w;
            w = wz4[k4];
            az0 = fmaf(h4.x, w.x, az0); az1 = fmaf(h4.y, w.y, az1);
            az0 = fmaf(h4.z, w.z, az0); az1 = fmaf(h4.w, w.w, az1);
            w = wr4[k4];
            ar0 = fmaf(h4.x, w.x, ar0); ar1 = fmaf(h4.y, w.y, ar1);
            ar0 = fmaf(h4.z, w.z, ar0); ar1 = fmaf(h4.w, w.w, ar1);
            w = wh4[k4];
            ah0 = fmaf(h4.x, w.x, ah0); ah1 = fmaf(h4.y, w.y, ah1);
            ah0 = fmaf(h4.z, w.z, ah0); ah1 = fmaf(h4.w, w.w, ah1);
        }
        float pz = az0 + az1, pr = ar0 + ar1, ph = ah0 + ah1;

        if (kh) {
            float4 v; v.x = pz; v.y = pr; v.z = ph; v.w = 0.f;
            *(float4*)&Red[((kh-1)*128 + tl)*4] = v;
        }
        __syncthreads();

        if (!kh) {
            float4 v1 = *(const float4*)&Red[(        tl)*4];
            float4 v2 = *(const float4*)&Red[(128  + tl)*4];
            float4 v3 = *(const float4*)&Red[(256  + tl)*4];
            float hz = pz + v1.x + v2.x + v3.x + bz;
            float hr = pr + v1.y + v2.y + v3.y + br;
            float hh = ph + v1.z + v2.z + v3.z + bh;
            float z    = fast_sigmoid(xz + hz);
            float r    = fast_sigmoid(xr + hr);
            float cand = fast_tanh(xh + r * hh);
            hn = fmaf(z, hn - cand, cand);      // z*h + (1-z)*cand

            // push to next-parity h buffer of every rank (incl. self)
            uint32_t off = off_self + (uint32_t)((p ^ 1) * BGR * KP * 4);
#pragma unroll
            for (int rr = 0; rr < CL; rr++) st_cluster_f32(peerH[rr] + off, hn);
        }

        __syncthreads();                 // all pushes issued CTA-wide
        if (tid < CL) mbar_arrive_cluster(peerM[tid]);

        // latency cover between arrive and wait: y store + next-x prefetch
        if (!kh) {
            y[((size_t)bglob*T_ + tt)*YCH + dir*256 + jglob] = hn;
            if (s + 1 < T_) {
                int tn = dir ? (T_-2-s) : (s+1);
                size_t xrow = ((size_t)bglob*T_ + tn) * X3;
                xz = __ldg(&xp[xrow +       jglob]);
                xr = __ldg(&xp[xrow + 256 + jglob]);
                xh = __ldg(&xp[xrow + 512 + jglob]);
            }
        }

        mbar_wait_parity(mbar, (uint32_t)(s & 1));
        p ^= 1;
    }

    if (kh == 0) {
        if (layer == 2)
            hcat[(size_t)bglob*YCH + dir*256 + jglob] = hn;
        else
            g_h[dir][bglob][jglob] = hn;
    }
    CLUSTER_ARRIVE_();   // keep smem alive until all peers' final pushes land
    CLUSTER_WAIT_();
}

// ---------------------------------------------------------------------------
// launch
// ---------------------------------------------------------------------------
extern "C" void kernel_launch(void* const* d_in, const int* in_sizes, int n_in,
                              void* d_out, int out_size)
{
    (void)in_sizes; (void)n_in; (void)out_size;
    const float* x = (const float*)d_in[0];
    const float* p[18];
    for (int i = 0; i < 18; i++) p[i] = (const float*)d_in[1 + i];
    // layer l: fwk=p[6l], fwr=p[6l+1], fwb=p[6l+2], bwk=p[6l+3], bwr=p[6l+4], bwb=p[6l+5]

    float* y    = (float*)d_out;                    // [B][T][512], inter-layer reuse
    float* hcat = y + (size_t)B_ * T_ * YCH;        // [B][512] final states

    cudaFuncSetAttribute(rec_kernel,
                         cudaFuncAttributeMaxDynamicSharedMemorySize,
                         REC_SMEM_BYTES);

    const int tot4 = B_*T_*X3/4;
    layer0_xp_kernel<<<(tot4 + 255)/256, 256>>>(x, p[0], p[2], p[3], p[5]);
    rec_kernel<<<128, REC_THREADS, REC_SMEM_BYTES>>>(p[1], p[2], p[4], p[5], y, hcat, 0);

    dim3 gg(X3/128, (B_*T_)/128, 2);
    gemm_xp_kernel<<<gg, 256>>>(y, p[6], p[8], p[9], p[11]);
    rec_kernel<<<128, REC_THREADS, REC_SMEM_BYTES>>>(p[7], p[8], p[10], p[11], y, hcat, 1);

    gemm_xp_kernel<<<gg, 256>>>(y, p[12], p[14], p[15], p[17]);
    rec_kernel<<<128, REC_THREADS, REC_SMEM_BYTES>>>(p[13], p[14], p[16], p[17], y, hcat, 2);
}

// round 6
// speedup vs baseline: 1.7338x; 1.0665x over previous
#include <cuda_runtime.h>
#include <cuda_bf16.h>
#include <cstdint>
#include <math.h>

#define U_  256
#define B_  32
#define T_  2048
#define X3  768      // 3U
#define YCH 512      // 2U
#define KP  260      // padded k-stride
#define CL  4        // cluster size (ranks)
#define CPR 64       // columns per rank
#define BGR 2        // batch rows per cluster
#define REC_THREADS 512
// smem floats: mbar pad(4) + W(192*KP) + H(2*BGR*KP) + Red(3*128*4)
#define SM_W    4
#define SM_H    (SM_W + 192*KP)
#define SM_RED  (SM_H + 2*BGR*KP)
#define REC_SMEM_FLOATS (SM_RED + 3*128*4)
#define REC_SMEM_BYTES  (REC_SMEM_FLOATS*4)

// Scratch: input projections per direction + inter-layer hidden states
__device__ float g_xp[2][B_*T_*X3];   // [dir][(b*T+t)*768 + c]
__device__ float g_h[2][B_][U_];      // final hidden state handoff between layers

// ---------------------------------------------------------------------------
// helpers
// ---------------------------------------------------------------------------
__device__ __forceinline__ uint32_t smem_u32(const void* p) {
    uint32_t a;
    asm("{ .reg .u64 t; cvta.to.shared.u64 t, %1; cvt.u32.u64 %0, t; }"
        : "=r"(a) : "l"(p));
    return a;
}
__device__ __forceinline__ uint32_t mapa_rank(uint32_t addr, int r) {
    uint32_t out;
    asm("mapa.shared::cluster.u32 %0, %1, %2;" : "=r"(out) : "r"(addr), "r"(r));
    return out;
}
__device__ __forceinline__ void st_cluster_f32(uint32_t addr, float v) {
    asm volatile("st.shared::cluster.f32 [%0], %1;" :: "r"(addr), "f"(v));
}
__device__ __forceinline__ uint32_t ctarank() {
    uint32_t r; asm("mov.u32 %0, %%cluster_ctarank;" : "=r"(r)); return r;
}
#define CLUSTER_ARRIVE_() asm volatile("barrier.cluster.arrive.aligned;" ::: "memory")
#define CLUSTER_WAIT_()   asm volatile("barrier.cluster.wait.aligned;"   ::: "memory")

__device__ __forceinline__ void mbar_init(uint32_t addr, uint32_t cnt) {
    asm volatile("mbarrier.init.shared.b64 [%0], %1;" :: "r"(addr), "r"(cnt) : "memory");
}
__device__ __forceinline__ void mbar_arrive_cluster(uint32_t addr) {
    asm volatile("mbarrier.arrive.release.cluster.shared::cluster.b64 _, [%0];"
                 :: "r"(addr) : "memory");
}
__device__ __forceinline__ void mbar_wait_parity(uint32_t addr, uint32_t parity) {
    asm volatile(
        "{\n\t"
        ".reg .pred P;\n\t"
        "WL%=:\n\t"
        "mbarrier.try_wait.parity.acquire.cluster.shared::cta.b64 P, [%0], %1, 0x989680;\n\t"
        "@!P bra WL%=;\n\t"
        "}"
        :: "r"(addr), "r"(parity) : "memory");
}

__device__ __forceinline__ float fast_sigmoid(float x) {
    return __fdividef(1.f, 1.f + __expf(-x));
}
__device__ __forceinline__ float fast_tanh(float x) {
    float e = __expf(-2.f * x);
    return __fdividef(1.f - e, 1.f + e);
}

// bf16 HMMA m16n8k16, fp32 accumulate (baseline PTX, legal on sm_100)
__device__ __forceinline__ void mma16816(float* c,
    uint32_t a0, uint32_t a1, uint32_t a2, uint32_t a3,
    uint32_t b0, uint32_t b1)
{
    asm volatile(
        "mma.sync.aligned.m16n8k16.row.col.f32.bf16.bf16.f32 "
        "{%0,%1,%2,%3}, {%4,%5,%6,%7}, {%8,%9}, {%0,%1,%2,%3};"
        : "+f"(c[0]), "+f"(c[1]), "+f"(c[2]), "+f"(c[3])
        : "r"(a0), "r"(a1), "r"(a2), "r"(a3), "r"(b0), "r"(b1));
}

// ---------------------------------------------------------------------------
// Layer 0 input projection: xp = x * Wk[0,:] + b[0,:]  (in_dim = 1)
// ---------------------------------------------------------------------------
__global__ void layer0_xp_kernel(const float* __restrict__ x,
                                 const float* __restrict__ fwk,
                                 const float* __restrict__ fwb,
                                 const float* __restrict__ bwk,
                                 const float* __restrict__ bwb)
{
    int i4 = blockIdx.x * blockDim.x + threadIdx.x;
    const int tot4 = B_*T_*X3/4;
    if (i4 >= tot4) return;
    int e  = i4 * 4;
    int c  = e % X3;
    int bt = e / X3;
    float xv = __ldg(&x[bt]);
    float4 kf = *(const float4*)&fwk[c];
    float4 bf = *(const float4*)&fwb[c];
    float4 kb = *(const float4*)&bwk[c];
    float4 bb = *(const float4*)&bwb[c];
    float4 of, ob;
    of.x = xv*kf.x + bf.x; of.y = xv*kf.y + bf.y;
    of.z = xv*kf.z + bf.z; of.w = xv*kf.w + bf.w;
    ob.x = xv*kb.x + bb.x; ob.y = xv*kb.y + bb.y;
    ob.z = xv*kb.z + bb.z; ob.w = xv*kb.w + bb.w;
    *(float4*)&g_xp[0][e] = of;
    *(float4*)&g_xp[1][e] = ob;
}

// ---------------------------------------------------------------------------
// Layers 1/2 input projection via bf16-split HMMA GEMM.
//   XP[dir] = Y(65536x512) @ Wk(512x768) + b0
//   D = Ah*Bh + Al*Bh + Ah*Bl  (fp32 accum; error ~2^-16)
//   BM=128, BN=128, BK=32; 256 threads = 8 warps (2 M x 4 N), warp = 64x32.
//   grid = (768/128, 65536/128, 2) = (6, 512, 2).
// ---------------------------------------------------------------------------
__global__ void __launch_bounds__(256) gemm_xp_mma_kernel(
    const float* __restrict__ Yin,
    const float* __restrict__ kfw, const float* __restrict__ bfw,
    const float* __restrict__ kbw, const float* __restrict__ bbw)
{
    // stride 40 halves (80B): quad fragment loads hit all 32 banks, no conflict
    __shared__ __nv_bfloat16 Ah[128][40], Al[128][40];
    __shared__ __nv_bfloat16 Bh[128][40], Bl[128][40];

    int dir = blockIdx.z;
    const float* Wk   = dir ? kbw : kfw;
    const float* bias = dir ? bbw : bfw;   // row 0 = input bias
    float* out = g_xp[dir];

    int n0 = blockIdx.x * 128;
    int m0 = blockIdx.y * 128;

    int tid  = threadIdx.x;
    int lane = tid & 31, wid = tid >> 5;
    int wm = wid >> 2, wn = wid & 3;       // warp tile: rows wm*64, cols wn*32
    int gr = lane >> 2, tc = (lane & 3) * 2;

    float acc[4][4][4];
#pragma unroll
    for (int i = 0; i < 4; i++)
#pragma unroll
        for (int j = 0; j < 4; j++)
#pragma unroll
            for (int q = 0; q < 4; q++) acc[i][j][q] = 0.f;

    for (int kt = 0; kt < 16; kt++) {
        int kc = kt * 32;
        // A tile: [128 rows m][32 k], k fastest -> coalesced
#pragma unroll
        for (int j = 0; j < 16; j++) {
            int i = tid + j * 256;
            int row = i >> 5, k = i & 31;
            float v = __ldg(&Yin[(size_t)(m0 + row)*YCH + kc + k]);
            __nv_bfloat16 hi = __float2bfloat16(v);
            Ah[row][k] = hi;
            Al[row][k] = __float2bfloat16(v - __bfloat162float(hi));
        }
        // B tile: smem as [n][k]; gmem Wk[k][n], n fastest -> coalesced
#pragma unroll
        for (int j = 0; j < 16; j++) {
            int i = tid + j * 256;
            int k = i >> 7, n = i & 127;
            float v = __ldg(&Wk[(size_t)(kc + k)*X3 + n0 + n]);
            __nv_bfloat16 hi = __float2bfloat16(v);
            Bh[n][k] = hi;
            Bl[n][k] = __float2bfloat16(v - __bfloat162float(hi));
        }
        __syncthreads();

#pragma unroll
        for (int kk = 0; kk < 32; kk += 16) {
            uint32_t bh0[4], bh1[4], bl0[4], bl1[4];
#pragma unroll
            for (int nf = 0; nf < 4; nf++) {
                int n = wn*32 + nf*8 + gr;
                bh0[nf] = *(const uint32_t*)&Bh[n][kk + tc];
                bh1[nf] = *(const uint32_t*)&Bh[n][kk + tc + 8];
                bl0[nf] = *(const uint32_t*)&Bl[n][kk + tc];
                bl1[nf] = *(const uint32_t*)&Bl[n][kk + tc + 8];
            }
#pragma unroll
            for (int mf = 0; mf < 4; mf++) {
                int r = wm*64 + mf*16 + gr;
                uint32_t ah0 = *(const uint32_t*)&Ah[r    ][kk + tc];
                uint32_t ah1 = *(const uint32_t*)&Ah[r + 8][kk + tc];
                uint32_t ah2 = *(const uint32_t*)&Ah[r    ][kk + tc + 8];
                uint32_t ah3 = *(const uint32_t*)&Ah[r + 8][kk + tc + 8];
                uint32_t al0 = *(const uint32_t*)&Al[r    ][kk + tc];
                uint32_t al1 = *(const uint32_t*)&Al[r + 8][kk + tc];
                uint32_t al2 = *(const uint32_t*)&Al[r    ][kk + tc + 8];
                uint32_t al3 = *(const uint32_t*)&Al[r + 8][kk + tc + 8];
#pragma unroll
                for (int nf = 0; nf < 4; nf++) {
                    mma16816(acc[mf][nf], ah0, ah1, ah2, ah3, bh0[nf], bh1[nf]);
                    mma16816(acc[mf][nf], al0, al1, al2, al3, bh0[nf], bh1[nf]);
                    mma16816(acc[mf][nf], ah0, ah1, ah2, ah3, bl0[nf], bl1[nf]);
                }
            }
        }
        __syncthreads();
    }

    // Epilogue: c0,c1 -> (row, col..col+1); c2,c3 -> (row+8, col..col+1)
#pragma unroll
    for (int mf = 0; mf < 4; mf++) {
        int row = m0 + wm*64 + mf*16 + gr;
#pragma unroll
        for (int nf = 0; nf < 4; nf++) {
            int col = n0 + wn*32 + nf*8 + tc;
            float b0 = __ldg(&bias[col]), b1 = __ldg(&bias[col + 1]);
            float2 lo, hi;
            lo.x = acc[mf][nf][0] + b0; lo.y = acc[mf][nf][1] + b1;
            hi.x = acc[mf][nf][2] + b0; hi.y = acc[mf][nf][3] + b1;
            *(float2*)&out[(size_t)row * X3 + col]       = lo;
            *(float2*)&out[(size_t)(row + 8) * X3 + col] = hi;
        }
    }
}

// ---------------------------------------------------------------------------
// Recurrence. Grid = 128 CTAs, clusters of 4, 512 threads. (unchanged R4)
// ---------------------------------------------------------------------------
__global__ void __cluster_dims__(CL, 1, 1) __launch_bounds__(REC_THREADS, 1)
rec_kernel(const float* __restrict__ wr_fw, const float* __restrict__ bias_fw,
           const float* __restrict__ wr_bw, const float* __restrict__ bias_bw,
           float* __restrict__ y, float* __restrict__ hcat, int layer)
{
    extern __shared__ float sm[];
    float* Wsm = sm + SM_W;          // [192][KP]
    float* Hsm = sm + SM_H;          // [2][BGR][KP]
    float* Red = sm + SM_RED;        // [3][128][4]
    uint32_t mbar = smem_u32(sm);    // 8B mbarrier at sm[0..1]

    int rank = (int)ctarank();
    int cidx = blockIdx.x >> 2;       // 0..31
    int dir  = cidx >> 4;             // 0 fw, 1 bw
    int bg   = cidx & 15;             // batch group (2 rows)
    int tid  = threadIdx.x;
    int kh   = tid >> 7;              // k-quarter 0..3
    int tl   = tid & 127;
    int jl   = tl >> 1;               // 0..63 local column
    int bl   = tl & 1;                // 0..1 local batch
    int jglob = rank*CPR + jl;
    int bglob = bg*BGR + bl;

    const float* Wr   = dir ? wr_bw   : wr_fw;
    const float* bias = dir ? bias_bw : bias_fw;
    const float* xp   = g_xp[dir];

    if (tid == 0) mbar_init(mbar, CL);

    // Load weight slice: Wsm[(g*64+j)*KP + k] = Wr[k][g*256 + rank*64 + j]
    for (int idx = tid; idx < 192*256; idx += REC_THREADS) {
        int k    = idx / 192;
        int r192 = idx - k*192;
        int g = r192 >> 6, j = r192 & 63;
        Wsm[(g*CPR + j)*KP + k] = __ldg(&Wr[k*X3 + g*256 + rank*CPR + j]);
    }
    // Initial hidden state into parity-0 buffer
    for (int i = tid; i < BGR*256; i += REC_THREADS) {
        int b = i >> 8, k = i & 255;
        Hsm[b*KP + k] = layer ? g_h[dir][bg*BGR + b][k] : 0.f;
    }
    // Recurrent biases (row 1 of bias array) — only needed by kh=0
    float bz = 0.f, br = 0.f, bh = 0.f;
    if (kh == 0) {
        bz = __ldg(&bias[X3 +       jglob]);
        br = __ldg(&bias[X3 + 256 + jglob]);
        bh = __ldg(&bias[X3 + 512 + jglob]);
    }
    __syncthreads();
    CLUSTER_ARRIVE_();   // all mbarriers initialised + H/W loaded cluster-wide
    CLUSTER_WAIT_();

    uint32_t hbase = smem_u32(Hsm);
    uint32_t peerH[CL], peerM[CL];
#pragma unroll
    for (int r = 0; r < CL; r++) {
        peerH[r] = mapa_rank(hbase, r);
        peerM[r] = mapa_rank(mbar, r);
    }
    uint32_t off_self = (uint32_t)((bl*KP + jglob) * 4);

    const float4* wz4 = (const float4*)(Wsm + (          jl)*KP) + kh*16;
    const float4* wr4 = (const float4*)(Wsm + ( CPR    + jl)*KP) + kh*16;
    const float4* wh4 = (const float4*)(Wsm + (2*CPR   + jl)*KP) + kh*16;

    // h(t-1) for this (jglob,bl) carried in-register by kh==0 threads
    float hn = (kh == 0) ? Hsm[bl*KP + jglob] : 0.f;

    // prefetch xp for step 0
    float xz = 0.f, xr = 0.f, xh = 0.f;
    if (kh == 0) {
        int tt0 = dir ? (T_-1) : 0;
        size_t xrow = ((size_t)bglob*T_ + tt0) * X3;
        xz = __ldg(&xp[xrow +       jglob]);
        xr = __ldg(&xp[xrow + 256 + jglob]);
        xh = __ldg(&xp[xrow + 512 + jglob]);
    }

    int p = 0;
    for (int s = 0; s < T_; s++) {
        int tt = dir ? (T_-1-s) : s;

        const float4* hv4 = (const float4*)(Hsm + (p*BGR + bl)*KP) + kh*16;
        float az0 = 0.f, az1 = 0.f, ar0 = 0.f, ar1 = 0.f, ah0 = 0.f, ah1 = 0.f;
#pragma unroll 4
        for (int k4 = 0; k4 < 16; k4++) {
            float4 h4 = hv4[k4];
            float4 w;
            w = wz4[k4];
            az0 = fmaf(h4.x, w.x, az0); az1 = fmaf(h4.y, w.y, az1);
            az0 = fmaf(h4.z, w.z, az0); az1 = fmaf(h4.w, w.w, az1);
            w = wr4[k4];
            ar0 = fmaf(h4.x, w.x, ar0); ar1 = fmaf(h4.y, w.y, ar1);
            ar0 = fmaf(h4.z, w.z, ar0); ar1 = fmaf(h4.w, w.w, ar1);
            w = wh4[k4];
            ah0 = fmaf(h4.x, w.x, ah0); ah1 = fmaf(h4.y, w.y, ah1);
            ah0 = fmaf(h4.z, w.z, ah0); ah1 = fmaf(h4.w, w.w, ah1);
        }
        float pz = az0 + az1, pr = ar0 + ar1, ph = ah0 + ah1;

        if (kh) {
            float4 v; v.x = pz; v.y = pr; v.z = ph; v.w = 0.f;
            *(float4*)&Red[((kh-1)*128 + tl)*4] = v;
        }
        __syncthreads();

        if (!kh) {
            float4 v1 = *(const float4*)&Red[(        tl)*4];
            float4 v2 = *(const float4*)&Red[(128  + tl)*4];
            float4 v3 = *(const float4*)&Red[(256  + tl)*4];
            float hz = pz + v1.x + v2.x + v3.x + bz;
            float hr = pr + v1.y + v2.y + v3.y + br;
            float hh = ph + v1.z + v2.z + v3.z + bh;
            float z    = fast_sigmoid(xz + hz);
            float r    = fast_sigmoid(xr + hr);
            float cand = fast_tanh(xh + r * hh);
            hn = fmaf(z, hn - cand, cand);      // z*h + (1-z)*cand

            // push to next-parity h buffer of every rank (incl. self)
            uint32_t off = off_self + (uint32_t)((p ^ 1) * BGR * KP * 4);
#pragma unroll
            for (int rr = 0; rr < CL; rr++) st_cluster_f32(peerH[rr] + off, hn);
        }

        __syncthreads();                 // all pushes issued CTA-wide
        if (tid < CL) mbar_arrive_cluster(peerM[tid]);

        // latency cover between arrive and wait: y store + next-x prefetch
        if (!kh) {
            y[((size_t)bglob*T_ + tt)*YCH + dir*256 + jglob] = hn;
            if (s + 1 < T_) {
                int tn = dir ? (T_-2-s) : (s+1);
                size_t xrow = ((size_t)bglob*T_ + tn) * X3;
                xz = __ldg(&xp[xrow +       jglob]);
                xr = __ldg(&xp[xrow + 256 + jglob]);
                xh = __ldg(&xp[xrow + 512 + jglob]);
            }
        }

        mbar_wait_parity(mbar, (uint32_t)(s & 1));
        p ^= 1;
    }

    if (kh == 0) {
        if (layer == 2)
            hcat[(size_t)bglob*YCH + dir*256 + jglob] = hn;
        else
            g_h[dir][bglob][jglob] = hn;
    }
    CLUSTER_ARRIVE_();   // keep smem alive until all peers' final pushes land
    CLUSTER_WAIT_();
}

// ---------------------------------------------------------------------------
// launch
// ---------------------------------------------------------------------------
extern "C" void kernel_launch(void* const* d_in, const int* in_sizes, int n_in,
                              void* d_out, int out_size)
{
    (void)in_sizes; (void)n_in; (void)out_size;
    const float* x = (const float*)d_in[0];
    const float* p[18];
    for (int i = 0; i < 18; i++) p[i] = (const float*)d_in[1 + i];
    // layer l: fwk=p[6l], fwr=p[6l+1], fwb=p[6l+2], bwk=p[6l+3], bwr=p[6l+4], bwb=p[6l+5]

    float* y    = (float*)d_out;                    // [B][T][512], inter-layer reuse
    float* hcat = y + (size_t)B_ * T_ * YCH;        // [B][512] final states

    cudaFuncSetAttribute(rec_kernel,
                         cudaFuncAttributeMaxDynamicSharedMemorySize,
                         REC_SMEM_BYTES);

    const int tot4 = B_*T_*X3/4;
    layer0_xp_kernel<<<(tot4 + 255)/256, 256>>>(x, p[0], p[2], p[3], p[5]);
    rec_kernel<<<128, REC_THREADS, REC_SMEM_BYTES>>>(p[1], p[2], p[4], p[5], y, hcat, 0);

    dim3 gg(X3/128, (B_*T_)/128, 2);
    gemm_xp_mma_kernel<<<gg, 256>>>(y, p[6], p[8], p[9], p[11]);
    rec_kernel<<<128, REC_THREADS, REC_SMEM_BYTES>>>(p[7], p[8], p[10], p[11], y, hcat, 1);

    gemm_xp_mma_kernel<<<gg, 256>>>(y, p[12], p[14], p[15], p[17]);
    rec_kernel<<<128, REC_THREADS, REC_SMEM_BYTES>>>(p[13], p[14], p[16], p[17], y, hcat, 2);
}

// round 7
// speedup vs baseline: 1.8111x; 1.0446x over previous
#include <cuda_runtime.h>
#include <cuda_bf16.h>
#include <cstdint>
#include <math.h>

#define U_  256
#define B_  32
#define T_  2048
#define X3  768      // 3U
#define YCH 512      // 2U
#define KP  260      // padded k-stride
#define CL  4        // cluster size (ranks)
#define CPR 64       // columns per rank
#define BGR 2        // batch rows per cluster
#define REC_THREADS 512
// smem floats: mbar pad(4) + W(192*KP) + H(2*BGR*KP) + Red(3*128*4)
#define SM_W    4
#define SM_H    (SM_W + 192*KP)
#define SM_RED  (SM_H + 2*BGR*KP)
#define REC_SMEM_FLOATS (SM_RED + 3*128*4)
#define REC_SMEM_BYTES  (REC_SMEM_FLOATS*4)

// Scratch: input projections per direction + inter-layer hidden states
__device__ float g_xp[2][B_*T_*X3];   // [dir][(b*T+t)*768 + c]
__device__ float g_h[2][B_][U_];      // final hidden state handoff between layers

// ---------------------------------------------------------------------------
// helpers
// ---------------------------------------------------------------------------
__device__ __forceinline__ uint32_t smem_u32(const void* p) {
    uint32_t a;
    asm("{ .reg .u64 t; cvta.to.shared.u64 t, %1; cvt.u32.u64 %0, t; }"
        : "=r"(a) : "l"(p));
    return a;
}
__device__ __forceinline__ uint32_t mapa_rank(uint32_t addr, int r) {
    uint32_t out;
    asm("mapa.shared::cluster.u32 %0, %1, %2;" : "=r"(out) : "r"(addr), "r"(r));
    return out;
}
__device__ __forceinline__ void st_cluster_f32(uint32_t addr, float v) {
    asm volatile("st.shared::cluster.f32 [%0], %1;" :: "r"(addr), "f"(v));
}
__device__ __forceinline__ uint32_t ctarank() {
    uint32_t r; asm("mov.u32 %0, %%cluster_ctarank;" : "=r"(r)); return r;
}
#define CLUSTER_ARRIVE_() asm volatile("barrier.cluster.arrive.aligned;" ::: "memory")
#define CLUSTER_WAIT_()   asm volatile("barrier.cluster.wait.aligned;"   ::: "memory")

__device__ __forceinline__ void mbar_init(uint32_t addr, uint32_t cnt) {
    asm volatile("mbarrier.init.shared.b64 [%0], %1;" :: "r"(addr), "r"(cnt) : "memory");
}
__device__ __forceinline__ void mbar_arrive_cluster(uint32_t addr) {
    asm volatile("mbarrier.arrive.release.cluster.shared::cluster.b64 _, [%0];"
                 :: "r"(addr) : "memory");
}
__device__ __forceinline__ void mbar_wait_parity(uint32_t addr, uint32_t parity) {
    asm volatile(
        "{\n\t"
        ".reg .pred P;\n\t"
        "WL%=:\n\t"
        "mbarrier.try_wait.parity.acquire.cluster.shared::cta.b64 P, [%0], %1, 0x989680;\n\t"
        "@!P bra WL%=;\n\t"
        "}"
        :: "r"(addr), "r"(parity) : "memory");
}

__device__ __forceinline__ float fast_sigmoid(float x) {
    return __fdividef(1.f, 1.f + __expf(-x));
}
__device__ __forceinline__ float fast_tanh(float x) {
    float e = __expf(-2.f * x);
    return __fdividef(1.f - e, 1.f + e);
}

// Packed dual fp32 FMA (Blackwell family, PTX ISA 8.6, sm_100+):
// d.lo += a.lo*b.lo ; d.hi += a.hi*b.hi  — IEEE fp32 per lane.
__device__ __forceinline__ void ffma2(unsigned long long& d,
                                      unsigned long long a,
                                      unsigned long long b) {
    asm("fma.rn.f32x2 %0, %1, %2, %0;" : "+l"(d) : "l"(a), "l"(b));
}
__device__ __forceinline__ float upk_sum(unsigned long long v) {
    float lo, hi;
    asm("mov.b64 {%0, %1}, %2;" : "=f"(lo), "=f"(hi) : "l"(v));
    return lo + hi;
}

// bf16 HMMA m16n8k16, fp32 accumulate (baseline PTX, legal on sm_100)
__device__ __forceinline__ void mma16816(float* c,
    uint32_t a0, uint32_t a1, uint32_t a2, uint32_t a3,
    uint32_t b0, uint32_t b1)
{
    asm volatile(
        "mma.sync.aligned.m16n8k16.row.col.f32.bf16.bf16.f32 "
        "{%0,%1,%2,%3}, {%4,%5,%6,%7}, {%8,%9}, {%0,%1,%2,%3};"
        : "+f"(c[0]), "+f"(c[1]), "+f"(c[2]), "+f"(c[3])
        : "r"(a0), "r"(a1), "r"(a2), "r"(a3), "r"(b0), "r"(b1));
}

// ---------------------------------------------------------------------------
// Layer 0 input projection: xp = x * Wk[0,:] + b[0,:]  (in_dim = 1)
// ---------------------------------------------------------------------------
__global__ void layer0_xp_kernel(const float* __restrict__ x,
                                 const float* __restrict__ fwk,
                                 const float* __restrict__ fwb,
                                 const float* __restrict__ bwk,
                                 const float* __restrict__ bwb)
{
    int i4 = blockIdx.x * blockDim.x + threadIdx.x;
    const int tot4 = B_*T_*X3/4;
    if (i4 >= tot4) return;
    int e  = i4 * 4;
    int c  = e % X3;
    int bt = e / X3;
    float xv = __ldg(&x[bt]);
    float4 kf = *(const float4*)&fwk[c];
    float4 bf = *(const float4*)&fwb[c];
    float4 kb = *(const float4*)&bwk[c];
    float4 bb = *(const float4*)&bwb[c];
    float4 of, ob;
    of.x = xv*kf.x + bf.x; of.y = xv*kf.y + bf.y;
    of.z = xv*kf.z + bf.z; of.w = xv*kf.w + bf.w;
    ob.x = xv*kb.x + bb.x; ob.y = xv*kb.y + bb.y;
    ob.z = xv*kb.z + bb.z; ob.w = xv*kb.w + bb.w;
    *(float4*)&g_xp[0][e] = of;
    *(float4*)&g_xp[1][e] = ob;
}

// ---------------------------------------------------------------------------
// Layers 1/2 input projection via bf16-split HMMA GEMM. (unchanged R6)
//   XP[dir] = Y(65536x512) @ Wk(512x768) + b0
//   D = Ah*Bh + Al*Bh + Ah*Bl  (fp32 accum; error ~2^-16)
// ---------------------------------------------------------------------------
__global__ void __launch_bounds__(256) gemm_xp_mma_kernel(
    const float* __restrict__ Yin,
    const float* __restrict__ kfw, const float* __restrict__ bfw,
    const float* __restrict__ kbw, const float* __restrict__ bbw)
{
    // stride 40 halves (80B): quad fragment loads hit all 32 banks, no conflict
    __shared__ __nv_bfloat16 Ah[128][40], Al[128][40];
    __shared__ __nv_bfloat16 Bh[128][40], Bl[128][40];

    int dir = blockIdx.z;
    const float* Wk   = dir ? kbw : kfw;
    const float* bias = dir ? bbw : bfw;   // row 0 = input bias
    float* out = g_xp[dir];

    int n0 = blockIdx.x * 128;
    int m0 = blockIdx.y * 128;

    int tid  = threadIdx.x;
    int lane = tid & 31, wid = tid >> 5;
    int wm = wid >> 2, wn = wid & 3;       // warp tile: rows wm*64, cols wn*32
    int gr = lane >> 2, tc = (lane & 3) * 2;

    float acc[4][4][4];
#pragma unroll
    for (int i = 0; i < 4; i++)
#pragma unroll
        for (int j = 0; j < 4; j++)
#pragma unroll
            for (int q = 0; q < 4; q++) acc[i][j][q] = 0.f;

    for (int kt = 0; kt < 16; kt++) {
        int kc = kt * 32;
        // A tile: [128 rows m][32 k], k fastest -> coalesced
#pragma unroll
        for (int j = 0; j < 16; j++) {
            int i = tid + j * 256;
            int row = i >> 5, k = i & 31;
            float v = __ldg(&Yin[(size_t)(m0 + row)*YCH + kc + k]);
            __nv_bfloat16 hi = __float2bfloat16(v);
            Ah[row][k] = hi;
            Al[row][k] = __float2bfloat16(v - __bfloat162float(hi));
        }
        // B tile: smem as [n][k]; gmem Wk[k][n], n fastest -> coalesced
#pragma unroll
        for (int j = 0; j < 16; j++) {
            int i = tid + j * 256;
            int k = i >> 7, n = i & 127;
            float v = __ldg(&Wk[(size_t)(kc + k)*X3 + n0 + n]);
            __nv_bfloat16 hi = __float2bfloat16(v);
            Bh[n][k] = hi;
            Bl[n][k] = __float2bfloat16(v - __bfloat162float(hi));
        }
        __syncthreads();

#pragma unroll
        for (int kk = 0; kk < 32; kk += 16) {
            uint32_t bh0[4], bh1[4], bl0[4], bl1[4];
#pragma unroll
            for (int nf = 0; nf < 4; nf++) {
                int n = wn*32 + nf*8 + gr;
                bh0[nf] = *(const uint32_t*)&Bh[n][kk + tc];
                bh1[nf] = *(const uint32_t*)&Bh[n][kk + tc + 8];
                bl0[nf] = *(const uint32_t*)&Bl[n][kk + tc];
                bl1[nf] = *(const uint32_t*)&Bl[n][kk + tc + 8];
            }
#pragma unroll
            for (int mf = 0; mf < 4; mf++) {
                int r = wm*64 + mf*16 + gr;
                uint32_t ah0 = *(const uint32_t*)&Ah[r    ][kk + tc];
                uint32_t ah1 = *(const uint32_t*)&Ah[r + 8][kk + tc];
                uint32_t ah2 = *(const uint32_t*)&Ah[r    ][kk + tc + 8];
                uint32_t ah3 = *(const uint32_t*)&Ah[r + 8][kk + tc + 8];
                uint32_t al0 = *(const uint32_t*)&Al[r    ][kk + tc];
                uint32_t al1 = *(const uint32_t*)&Al[r + 8][kk + tc];
                uint32_t al2 = *(const uint32_t*)&Al[r    ][kk + tc + 8];
                uint32_t al3 = *(const uint32_t*)&Al[r + 8][kk + tc + 8];
#pragma unroll
                for (int nf = 0; nf < 4; nf++) {
                    mma16816(acc[mf][nf], ah0, ah1, ah2, ah3, bh0[nf], bh1[nf]);
                    mma16816(acc[mf][nf], al0, al1, al2, al3, bh0[nf], bh1[nf]);
                    mma16816(acc[mf][nf], ah0, ah1, ah2, ah3, bl0[nf], bl1[nf]);
                }
            }
        }
        __syncthreads();
    }

    // Epilogue: c0,c1 -> (row, col..col+1); c2,c3 -> (row+8, col..col+1)
#pragma unroll
    for (int mf = 0; mf < 4; mf++) {
        int row = m0 + wm*64 + mf*16 + gr;
#pragma unroll
        for (int nf = 0; nf < 4; nf++) {
            int col = n0 + wn*32 + nf*8 + tc;
            float b0 = __ldg(&bias[col]), b1 = __ldg(&bias[col + 1]);
            float2 lo, hi;
            lo.x = acc[mf][nf][0] + b0; lo.y = acc[mf][nf][1] + b1;
            hi.x = acc[mf][nf][2] + b0; hi.y = acc[mf][nf][3] + b1;
            *(float2*)&out[(size_t)row * X3 + col]       = lo;
            *(float2*)&out[(size_t)(row + 8) * X3 + col] = hi;
        }
    }
}

// ---------------------------------------------------------------------------
// Recurrence. Grid = 128 CTAs, clusters of 4, 512 threads.
//   Same protocol as R4; dot products now use packed fma.rn.f32x2
//   (k-pair packing: 6 FFMA2 + 4 LDS.128 per k4-iter, fp32-exact).
// ---------------------------------------------------------------------------
__global__ void __cluster_dims__(CL, 1, 1) __launch_bounds__(REC_THREADS, 1)
rec_kernel(const float* __restrict__ wr_fw, const float* __restrict__ bias_fw,
           const float* __restrict__ wr_bw, const float* __restrict__ bias_bw,
           float* __restrict__ y, float* __restrict__ hcat, int layer)
{
    extern __shared__ float sm[];
    float* Wsm = sm + SM_W;          // [192][KP]
    float* Hsm = sm + SM_H;          // [2][BGR][KP]
    float* Red = sm + SM_RED;        // [3][128][4]
    uint32_t mbar = smem_u32(sm);    // 8B mbarrier at sm[0..1]

    int rank = (int)ctarank();
    int cidx = blockIdx.x >> 2;       // 0..31
    int dir  = cidx >> 4;             // 0 fw, 1 bw
    int bg   = cidx & 15;             // batch group (2 rows)
    int tid  = threadIdx.x;
    int kh   = tid >> 7;              // k-quarter 0..3
    int tl   = tid & 127;
    int jl   = tl >> 1;               // 0..63 local column
    int bl   = tl & 1;                // 0..1 local batch
    int jglob = rank*CPR + jl;
    int bglob = bg*BGR + bl;

    const float* Wr   = dir ? wr_bw   : wr_fw;
    const float* bias = dir ? bias_bw : bias_fw;
    const float* xp   = g_xp[dir];

    if (tid == 0) mbar_init(mbar, CL);

    // Load weight slice: Wsm[(g*64+j)*KP + k] = Wr[k][g*256 + rank*64 + j]
    for (int idx = tid; idx < 192*256; idx += REC_THREADS) {
        int k    = idx / 192;
        int r192 = idx - k*192;
        int g = r192 >> 6, j = r192 & 63;
        Wsm[(g*CPR + j)*KP + k] = __ldg(&Wr[k*X3 + g*256 + rank*CPR + j]);
    }
    // Initial hidden state into parity-0 buffer
    for (int i = tid; i < BGR*256; i += REC_THREADS) {
        int b = i >> 8, k = i & 255;
        Hsm[b*KP + k] = layer ? g_h[dir][bg*BGR + b][k] : 0.f;
    }
    // Recurrent biases (row 1 of bias array) — only needed by kh=0
    float bz = 0.f, br = 0.f, bh = 0.f;
    if (kh == 0) {
        bz = __ldg(&bias[X3 +       jglob]);
        br = __ldg(&bias[X3 + 256 + jglob]);
        bh = __ldg(&bias[X3 + 512 + jglob]);
    }
    __syncthreads();
    CLUSTER_ARRIVE_();   // all mbarriers initialised + H/W loaded cluster-wide
    CLUSTER_WAIT_();

    uint32_t hbase = smem_u32(Hsm);
    uint32_t peerH[CL], peerM[CL];
#pragma unroll
    for (int r = 0; r < CL; r++) {
        peerH[r] = mapa_rank(hbase, r);
        peerM[r] = mapa_rank(mbar, r);
    }
    uint32_t off_self = (uint32_t)((bl*KP + jglob) * 4);

    // packed-pair views of weight rows (16B = 2 x f32x2 lanes)
    const ulonglong2* wz2 = (const ulonglong2*)(Wsm + (          jl)*KP) + kh*16;
    const ulonglong2* wr2 = (const ulonglong2*)(Wsm + ( CPR    + jl)*KP) + kh*16;
    const ulonglong2* wh2 = (const ulonglong2*)(Wsm + (2*CPR   + jl)*KP) + kh*16;

    // h(t-1) for this (jglob,bl) carried in-register by kh==0 threads
    float hn = (kh == 0) ? Hsm[bl*KP + jglob] : 0.f;

    // prefetch xp for step 0
    float xz = 0.f, xr = 0.f, xh = 0.f;
    if (kh == 0) {
        int tt0 = dir ? (T_-1) : 0;
        size_t xrow = ((size_t)bglob*T_ + tt0) * X3;
        xz = __ldg(&xp[xrow +       jglob]);
        xr = __ldg(&xp[xrow + 256 + jglob]);
        xh = __ldg(&xp[xrow + 512 + jglob]);
    }

    int p = 0;
    for (int s = 0; s < T_; s++) {
        int tt = dir ? (T_-1-s) : s;

        const ulonglong2* hv2 =
            (const ulonglong2*)(Hsm + (p*BGR + bl)*KP) + kh*16;
        unsigned long long az0 = 0ull, az1 = 0ull;
        unsigned long long ar0 = 0ull, ar1 = 0ull;
        unsigned long long ah0 = 0ull, ah1 = 0ull;
#pragma unroll
        for (int k4 = 0; k4 < 16; k4++) {
            ulonglong2 h2 = hv2[k4];
            ulonglong2 w;
            w = wz2[k4]; ffma2(az0, w.x, h2.x); ffma2(az1, w.y, h2.y);
            w = wr2[k4]; ffma2(ar0, w.x, h2.x); ffma2(ar1, w.y, h2.y);
            w = wh2[k4]; ffma2(ah0, w.x, h2.x); ffma2(ah1, w.y, h2.y);
        }
        float pz = upk_sum(az0) + upk_sum(az1);
        float pr = upk_sum(ar0) + upk_sum(ar1);
        float ph = upk_sum(ah0) + upk_sum(ah1);

        if (kh) {
            float4 v; v.x = pz; v.y = pr; v.z = ph; v.w = 0.f;
            *(float4*)&Red[((kh-1)*128 + tl)*4] = v;
        }
        __syncthreads();

        if (!kh) {
            float4 v1 = *(const float4*)&Red[(        tl)*4];
            float4 v2 = *(const float4*)&Red[(128  + tl)*4];
            float4 v3 = *(const float4*)&Red[(256  + tl)*4];
            float hz = pz + v1.x + v2.x + v3.x + bz;
            float hr = pr + v1.y + v2.y + v3.y + br;
            float hh = ph + v1.z + v2.z + v3.z + bh;
            float z    = fast_sigmoid(xz + hz);
            float r    = fast_sigmoid(xr + hr);
            float cand = fast_tanh(xh + r * hh);
            hn = fmaf(z, hn - cand, cand);      // z*h + (1-z)*cand

            // push to next-parity h buffer of every rank (incl. self)
            uint32_t off = off_self + (uint32_t)((p ^ 1) * BGR * KP * 4);
#pragma unroll
            for (int rr = 0; rr < CL; rr++) st_cluster_f32(peerH[rr] + off, hn);
        }

        __syncthreads();                 // all pushes issued CTA-wide
        if (tid < CL) mbar_arrive_cluster(peerM[tid]);

        // latency cover between arrive and wait: y store + next-x prefetch
        if (!kh) {
            y[((size_t)bglob*T_ + tt)*YCH + dir*256 + jglob] = hn;
            if (s + 1 < T_) {
                int tn = dir ? (T_-2-s) : (s+1);
                size_t xrow = ((size_t)bglob*T_ + tn) * X3;
                xz = __ldg(&xp[xrow +       jglob]);
                xr = __ldg(&xp[xrow + 256 + jglob]);
                xh = __ldg(&xp[xrow + 512 + jglob]);
            }
        }

        mbar_wait_parity(mbar, (uint32_t)(s & 1));
        p ^= 1;
    }

    if (kh == 0) {
        if (layer == 2)
            hcat[(size_t)bglob*YCH + dir*256 + jglob] = hn;
        else
            g_h[dir][bglob][jglob] = hn;
    }
    CLUSTER_ARRIVE_();   // keep smem alive until all peers' final pushes land
    CLUSTER_WAIT_();
}

// ---------------------------------------------------------------------------
// launch
// ---------------------------------------------------------------------------
extern "C" void kernel_launch(void* const* d_in, const int* in_sizes, int n_in,
                              void* d_out, int out_size)
{
    (void)in_sizes; (void)n_in; (void)out_size;
    const float* x = (const float*)d_in[0];
    const float* p[18];
    for (int i = 0; i < 18; i++) p[i] = (const float*)d_in[1 + i];
    // layer l: fwk=p[6l], fwr=p[6l+1], fwb=p[6l+2], bwk=p[6l+3], bwr=p[6l+4], bwb=p[6l+5]

    float* y    = (float*)d_out;                    // [B][T][512], inter-layer reuse
    float* hcat = y + (size_t)B_ * T_ * YCH;        // [B][512] final states

    cudaFuncSetAttribute(rec_kernel,
                         cudaFuncAttributeMaxDynamicSharedMemorySize,
                         REC_SMEM_BYTES);

    const int tot4 = B_*T_*X3/4;
    layer0_xp_kernel<<<(tot4 + 255)/256, 256>>>(x, p[0], p[2], p[3], p[5]);
    rec_kernel<<<128, REC_THREADS, REC_SMEM_BYTES>>>(p[1], p[2], p[4], p[5], y, hcat, 0);

    dim3 gg(X3/128, (B_*T_)/128, 2);
    gemm_xp_mma_kernel<<<gg, 256>>>(y, p[6], p[8], p[9], p[11]);
    rec_kernel<<<128, REC_THREADS, REC_SMEM_BYTES>>>(p[7], p[8], p[10], p[11], y, hcat, 1);

    gemm_xp_mma_kernel<<<gg, 256>>>(y, p[12], p[14], p[15], p[17]);
    rec_kernel<<<128, REC_THREADS, REC_SMEM_BYTES>>>(p[13], p[14], p[16], p[17], y, hcat, 2);
}

// round 8
// speedup vs baseline: 1.8264x; 1.0084x over previous
#include <cuda_runtime.h>
#include <cuda_bf16.h>
#include <cstdint>
#include <math.h>

#define U_  256
#define B_  32
#define T_  2048
#define X3  768      // 3U
#define YCH 512      // 2U
#define KP  260      // padded k-stride
#define CL  4        // cluster size (ranks)
#define CPR 64       // columns per rank
#define BGR 2        // batch rows per cluster
#define REC_THREADS 512
// smem floats: mbar pad(4) + W(192*KP) + H(2*BGR*KP) + Red(3*128*4)
#define SM_W    4
#define SM_H    (SM_W + 192*KP)
#define SM_RED  (SM_H + 2*BGR*KP)
#define REC_SMEM_FLOATS (SM_RED + 3*128*4)
#define REC_SMEM_BYTES  (REC_SMEM_FLOATS*4)

// Scratch: input projections per direction + inter-layer hidden states
__device__ float g_xp[2][B_*T_*X3];   // [dir][(b*T+t)*768 + c]
__device__ float g_h[2][B_][U_];      // final hidden state handoff between layers

// ---------------------------------------------------------------------------
// helpers
// ---------------------------------------------------------------------------
__device__ __forceinline__ uint32_t smem_u32(const void* p) {
    uint32_t a;
    asm("{ .reg .u64 t; cvta.to.shared.u64 t, %1; cvt.u32.u64 %0, t; }"
        : "=r"(a) : "l"(p));
    return a;
}
__device__ __forceinline__ uint32_t mapa_rank(uint32_t addr, int r) {
    uint32_t out;
    asm("mapa.shared::cluster.u32 %0, %1, %2;" : "=r"(out) : "r"(addr), "r"(r));
    return out;
}
__device__ __forceinline__ void st_cluster_f32(uint32_t addr, float v) {
    asm volatile("st.shared::cluster.f32 [%0], %1;" :: "r"(addr), "f"(v));
}
__device__ __forceinline__ uint32_t ctarank() {
    uint32_t r; asm("mov.u32 %0, %%cluster_ctarank;" : "=r"(r)); return r;
}
#define CLUSTER_ARRIVE_() asm volatile("barrier.cluster.arrive.aligned;" ::: "memory")
#define CLUSTER_WAIT_()   asm volatile("barrier.cluster.wait.aligned;"   ::: "memory")

__device__ __forceinline__ void mbar_init(uint32_t addr, uint32_t cnt) {
    asm volatile("mbarrier.init.shared.b64 [%0], %1;" :: "r"(addr), "r"(cnt) : "memory");
}
__device__ __forceinline__ void mbar_arrive_cluster(uint32_t addr) {
    asm volatile("mbarrier.arrive.release.cluster.shared::cluster.b64 _, [%0];"
                 :: "r"(addr) : "memory");
}
__device__ __forceinline__ void mbar_wait_parity(uint32_t addr, uint32_t parity) {
    asm volatile(
        "{\n\t"
        ".reg .pred P;\n\t"
        "WL%=:\n\t"
        "mbarrier.try_wait.parity.acquire.cluster.shared::cta.b64 P, [%0], %1, 0x989680;\n\t"
        "@!P bra WL%=;\n\t"
        "}"
        :: "r"(addr), "r"(parity) : "memory");
}

__device__ __forceinline__ float fast_sigmoid(float x) {
    return __fdividef(1.f, 1.f + __expf(-x));
}
__device__ __forceinline__ float fast_tanh(float x) {
    float e = __expf(-2.f * x);
    return __fdividef(1.f - e, 1.f + e);
}

// Packed dual fp32 FMA (Blackwell family, PTX ISA 8.6, sm_100+):
// d.lo += a.lo*b.lo ; d.hi += a.hi*b.hi  — IEEE fp32 per lane.
__device__ __forceinline__ void ffma2(unsigned long long& d,
                                      unsigned long long a,
                                      unsigned long long b) {
    asm("fma.rn.f32x2 %0, %1, %2, %0;" : "+l"(d) : "l"(a), "l"(b));
}
__device__ __forceinline__ float upk_sum(unsigned long long v) {
    float lo, hi;
    asm("mov.b64 {%0, %1}, %2;" : "=f"(lo), "=f"(hi) : "l"(v));
    return lo + hi;
}

// bf16 HMMA m16n8k16, fp32 accumulate (baseline PTX, legal on sm_100)
__device__ __forceinline__ void mma16816(float* c,
    uint32_t a0, uint32_t a1, uint32_t a2, uint32_t a3,
    uint32_t b0, uint32_t b1)
{
    asm volatile(
        "mma.sync.aligned.m16n8k16.row.col.f32.bf16.bf16.f32 "
        "{%0,%1,%2,%3}, {%4,%5,%6,%7}, {%8,%9}, {%0,%1,%2,%3};"
        : "+f"(c[0]), "+f"(c[1]), "+f"(c[2]), "+f"(c[3])
        : "r"(a0), "r"(a1), "r"(a2), "r"(a3), "r"(b0), "r"(b1));
}

// ---------------------------------------------------------------------------
// Layer 0 input projection: xp = x * Wk[0,:] + b[0,:]  (in_dim = 1)
// ---------------------------------------------------------------------------
__global__ void layer0_xp_kernel(const float* __restrict__ x,
                                 const float* __restrict__ fwk,
                                 const float* __restrict__ fwb,
                                 const float* __restrict__ bwk,
                                 const float* __restrict__ bwb)
{
    int i4 = blockIdx.x * blockDim.x + threadIdx.x;
    const int tot4 = B_*T_*X3/4;
    if (i4 >= tot4) return;
    int e  = i4 * 4;
    int c  = e % X3;
    int bt = e / X3;
    float xv = __ldg(&x[bt]);
    float4 kf = *(const float4*)&fwk[c];
    float4 bf = *(const float4*)&fwb[c];
    float4 kb = *(const float4*)&bwk[c];
    float4 bb = *(const float4*)&bwb[c];
    float4 of, ob;
    of.x = xv*kf.x + bf.x; of.y = xv*kf.y + bf.y;
    of.z = xv*kf.z + bf.z; of.w = xv*kf.w + bf.w;
    ob.x = xv*kb.x + bb.x; ob.y = xv*kb.y + bb.y;
    ob.z = xv*kb.z + bb.z; ob.w = xv*kb.w + bb.w;
    *(float4*)&g_xp[0][e] = of;
    *(float4*)&g_xp[1][e] = ob;
}

// ---------------------------------------------------------------------------
// Layers 1/2 input projection via bf16-split HMMA GEMM.
//   XP[dir] = Y(65536x512) @ Wk(512x768) + b0
//   D = Ah*Bh + Al*Bh + Ah*Bl  (fp32 accum; error ~2^-16)
//   R8: term-major MMA ordering — accumulator reuse distance 16 MMAs
//   (was 1), hiding HMMA latency.
// ---------------------------------------------------------------------------
__global__ void __launch_bounds__(256) gemm_xp_mma_kernel(
    const float* __restrict__ Yin,
    const float* __restrict__ kfw, const float* __restrict__ bfw,
    const float* __restrict__ kbw, const float* __restrict__ bbw)
{
    // stride 40 halves (80B): quad fragment loads hit all 32 banks, no conflict
    __shared__ __nv_bfloat16 Ah[128][40], Al[128][40];
    __shared__ __nv_bfloat16 Bh[128][40], Bl[128][40];

    int dir = blockIdx.z;
    const float* Wk   = dir ? kbw : kfw;
    const float* bias = dir ? bbw : bfw;   // row 0 = input bias
    float* out = g_xp[dir];

    int n0 = blockIdx.x * 128;
    int m0 = blockIdx.y * 128;

    int tid  = threadIdx.x;
    int lane = tid & 31, wid = tid >> 5;
    int wm = wid >> 2, wn = wid & 3;       // warp tile: rows wm*64, cols wn*32
    int gr = lane >> 2, tc = (lane & 3) * 2;

    float acc[4][4][4];
#pragma unroll
    for (int i = 0; i < 4; i++)
#pragma unroll
        for (int j = 0; j < 4; j++)
#pragma unroll
            for (int q = 0; q < 4; q++) acc[i][j][q] = 0.f;

    for (int kt = 0; kt < 16; kt++) {
        int kc = kt * 32;
        // A tile: [128 rows m][32 k], k fastest -> coalesced
#pragma unroll
        for (int j = 0; j < 16; j++) {
            int i = tid + j * 256;
            int row = i >> 5, k = i & 31;
            float v = __ldg(&Yin[(size_t)(m0 + row)*YCH + kc + k]);
            __nv_bfloat16 hi = __float2bfloat16(v);
            Ah[row][k] = hi;
            Al[row][k] = __float2bfloat16(v - __bfloat162float(hi));
        }
        // B tile: smem as [n][k]; gmem Wk[k][n], n fastest -> coalesced
#pragma unroll
        for (int j = 0; j < 16; j++) {
            int i = tid + j * 256;
            int k = i >> 7, n = i & 127;
            float v = __ldg(&Wk[(size_t)(kc + k)*X3 + n0 + n]);
            __nv_bfloat16 hi = __float2bfloat16(v);
            Bh[n][k] = hi;
            Bl[n][k] = __float2bfloat16(v - __bfloat162float(hi));
        }
        __syncthreads();

#pragma unroll
        for (int kk = 0; kk < 32; kk += 16) {
            // Load ALL fragments for this kk-half first
            uint32_t fbh[4][2], fbl[4][2];
#pragma unroll
            for (int nf = 0; nf < 4; nf++) {
                int n = wn*32 + nf*8 + gr;
                fbh[nf][0] = *(const uint32_t*)&Bh[n][kk + tc];
                fbh[nf][1] = *(const uint32_t*)&Bh[n][kk + tc + 8];
                fbl[nf][0] = *(const uint32_t*)&Bl[n][kk + tc];
                fbl[nf][1] = *(const uint32_t*)&Bl[n][kk + tc + 8];
            }
            uint32_t fah[4][4], fal[4][4];
#pragma unroll
            for (int mf = 0; mf < 4; mf++) {
                int r = wm*64 + mf*16 + gr;
                fah[mf][0] = *(const uint32_t*)&Ah[r    ][kk + tc];
                fah[mf][1] = *(const uint32_t*)&Ah[r + 8][kk + tc];
                fah[mf][2] = *(const uint32_t*)&Ah[r    ][kk + tc + 8];
                fah[mf][3] = *(const uint32_t*)&Ah[r + 8][kk + tc + 8];
                fal[mf][0] = *(const uint32_t*)&Al[r    ][kk + tc];
                fal[mf][1] = *(const uint32_t*)&Al[r + 8][kk + tc];
                fal[mf][2] = *(const uint32_t*)&Al[r    ][kk + tc + 8];
                fal[mf][3] = *(const uint32_t*)&Al[r + 8][kk + tc + 8];
            }
            // Term 1: Ah*Bh — 16 independent accumulators
#pragma unroll
            for (int mf = 0; mf < 4; mf++)
#pragma unroll
                for (int nf = 0; nf < 4; nf++)
                    mma16816(acc[mf][nf], fah[mf][0], fah[mf][1], fah[mf][2],
                             fah[mf][3], fbh[nf][0], fbh[nf][1]);
            // Term 2: Al*Bh
#pragma unroll
            for (int mf = 0; mf < 4; mf++)
#pragma unroll
                for (int nf = 0; nf < 4; nf++)
                    mma16816(acc[mf][nf], fal[mf][0], fal[mf][1], fal[mf][2],
                             fal[mf][3], fbh[nf][0], fbh[nf][1]);
            // Term 3: Ah*Bl
#pragma unroll
            for (int mf = 0; mf < 4; mf++)
#pragma unroll
                for (int nf = 0; nf < 4; nf++)
                    mma16816(acc[mf][nf], fah[mf][0], fah[mf][1], fah[mf][2],
                             fah[mf][3], fbl[nf][0], fbl[nf][1]);
        }
        __syncthreads();
    }

    // Epilogue: c0,c1 -> (row, col..col+1); c2,c3 -> (row+8, col..col+1)
#pragma unroll
    for (int mf = 0; mf < 4; mf++) {
        int row = m0 + wm*64 + mf*16 + gr;
#pragma unroll
        for (int nf = 0; nf < 4; nf++) {
            int col = n0 + wn*32 + nf*8 + tc;
            float b0 = __ldg(&bias[col]), b1 = __ldg(&bias[col + 1]);
            float2 lo, hi;
            lo.x = acc[mf][nf][0] + b0; lo.y = acc[mf][nf][1] + b1;
            hi.x = acc[mf][nf][2] + b0; hi.y = acc[mf][nf][3] + b1;
            *(float2*)&out[(size_t)row * X3 + col]       = lo;
            *(float2*)&out[(size_t)(row + 8) * X3 + col] = hi;
        }
    }
}

// ---------------------------------------------------------------------------
// Recurrence. Grid = 128 CTAs, clusters of 4, 512 threads. (unchanged R7)
// ---------------------------------------------------------------------------
__global__ void __cluster_dims__(CL, 1, 1) __launch_bounds__(REC_THREADS, 1)
rec_kernel(const float* __restrict__ wr_fw, const float* __restrict__ bias_fw,
           const float* __restrict__ wr_bw, const float* __restrict__ bias_bw,
           float* __restrict__ y, float* __restrict__ hcat, int layer)
{
    extern __shared__ float sm[];
    float* Wsm = sm + SM_W;          // [192][KP]
    float* Hsm = sm + SM_H;          // [2][BGR][KP]
    float* Red = sm + SM_RED;        // [3][128][4]
    uint32_t mbar = smem_u32(sm);    // 8B mbarrier at sm[0..1]

    int rank = (int)ctarank();
    int cidx = blockIdx.x >> 2;       // 0..31
    int dir  = cidx >> 4;             // 0 fw, 1 bw
    int bg   = cidx & 15;             // batch group (2 rows)
    int tid  = threadIdx.x;
    int kh   = tid >> 7;              // k-quarter 0..3
    int tl   = tid & 127;
    int jl   = tl >> 1;               // 0..63 local column
    int bl   = tl & 1;                // 0..1 local batch
    int jglob = rank*CPR + jl;
    int bglob = bg*BGR + bl;

    const float* Wr   = dir ? wr_bw   : wr_fw;
    const float* bias = dir ? bias_bw : bias_fw;
    const float* xp   = g_xp[dir];

    if (tid == 0) mbar_init(mbar, CL);

    // Load weight slice: Wsm[(g*64+j)*KP + k] = Wr[k][g*256 + rank*64 + j]
    for (int idx = tid; idx < 192*256; idx += REC_THREADS) {
        int k    = idx / 192;
        int r192 = idx - k*192;
        int g = r192 >> 6, j = r192 & 63;
        Wsm[(g*CPR + j)*KP + k] = __ldg(&Wr[k*X3 + g*256 + rank*CPR + j]);
    }
    // Initial hidden state into parity-0 buffer
    for (int i = tid; i < BGR*256; i += REC_THREADS) {
        int b = i >> 8, k = i & 255;
        Hsm[b*KP + k] = layer ? g_h[dir][bg*BGR + b][k] : 0.f;
    }
    // Recurrent biases (row 1 of bias array) — only needed by kh=0
    float bz = 0.f, br = 0.f, bh = 0.f;
    if (kh == 0) {
        bz = __ldg(&bias[X3 +       jglob]);
        br = __ldg(&bias[X3 + 256 + jglob]);
        bh = __ldg(&bias[X3 + 512 + jglob]);
    }
    __syncthreads();
    CLUSTER_ARRIVE_();   // all mbarriers initialised + H/W loaded cluster-wide
    CLUSTER_WAIT_();

    uint32_t hbase = smem_u32(Hsm);
    uint32_t peerH[CL], peerM[CL];
#pragma unroll
    for (int r = 0; r < CL; r++) {
        peerH[r] = mapa_rank(hbase, r);
        peerM[r] = mapa_rank(mbar, r);
    }
    uint32_t off_self = (uint32_t)((bl*KP + jglob) * 4);

    // packed-pair views of weight rows (16B = 2 x f32x2 lanes)
    const ulonglong2* wz2 = (const ulonglong2*)(Wsm + (          jl)*KP) + kh*16;
    const ulonglong2* wr2 = (const ulonglong2*)(Wsm + ( CPR    + jl)*KP) + kh*16;
    const ulonglong2* wh2 = (const ulonglong2*)(Wsm + (2*CPR   + jl)*KP) + kh*16;

    // h(t-1) for this (jglob,bl) carried in-register by kh==0 threads
    float hn = (kh == 0) ? Hsm[bl*KP + jglob] : 0.f;

    // prefetch xp for step 0
    float xz = 0.f, xr = 0.f, xh = 0.f;
    if (kh == 0) {
        int tt0 = dir ? (T_-1) : 0;
        size_t xrow = ((size_t)bglob*T_ + tt0) * X3;
        xz = __ldg(&xp[xrow +       jglob]);
        xr = __ldg(&xp[xrow + 256 + jglob]);
        xh = __ldg(&xp[xrow + 512 + jglob]);
    }

    int p = 0;
    for (int s = 0; s < T_; s++) {
        int tt = dir ? (T_-1-s) : s;

        const ulonglong2* hv2 =
            (const ulonglong2*)(Hsm + (p*BGR + bl)*KP) + kh*16;
        unsigned long long az0 = 0ull, az1 = 0ull;
        unsigned long long ar0 = 0ull, ar1 = 0ull;
        unsigned long long ah0 = 0ull, ah1 = 0ull;
#pragma unroll
        for (int k4 = 0; k4 < 16; k4++) {
            ulonglong2 h2 = hv2[k4];
            ulonglong2 w;
            w = wz2[k4]; ffma2(az0, w.x, h2.x); ffma2(az1, w.y, h2.y);
            w = wr2[k4]; ffma2(ar0, w.x, h2.x); ffma2(ar1, w.y, h2.y);
            w = wh2[k4]; ffma2(ah0, w.x, h2.x); ffma2(ah1, w.y, h2.y);
        }
        float pz = upk_sum(az0) + upk_sum(az1);
        float pr = upk_sum(ar0) + upk_sum(ar1);
        float ph = upk_sum(ah0) + upk_sum(ah1);

        if (kh) {
            float4 v; v.x = pz; v.y = pr; v.z = ph; v.w = 0.f;
            *(float4*)&Red[((kh-1)*128 + tl)*4] = v;
        }
        __syncthreads();

        if (!kh) {
            float4 v1 = *(const float4*)&Red[(        tl)*4];
            float4 v2 = *(const float4*)&Red[(128  + tl)*4];
            float4 v3 = *(const float4*)&Red[(256  + tl)*4];
            float hz = pz + v1.x + v2.x + v3.x + bz;
            float hr = pr + v1.y + v2.y + v3.y + br;
            float hh = ph + v1.z + v2.z + v3.z + bh;
            float z    = fast_sigmoid(xz + hz);
            float r    = fast_sigmoid(xr + hr);
            float cand = fast_tanh(xh + r * hh);
            hn = fmaf(z, hn - cand, cand);      // z*h + (1-z)*cand

            // push to next-parity h buffer of every rank (incl. self)
            uint32_t off = off_self + (uint32_t)((p ^ 1) * BGR * KP * 4);
#pragma unroll
            for (int rr = 0; rr < CL; rr++) st_cluster_f32(peerH[rr] + off, hn);
        }

        __syncthreads();                 // all pushes issued CTA-wide
        if (tid < CL) mbar_arrive_cluster(peerM[tid]);

        // latency cover between arrive and wait: y store + next-x prefetch
        if (!kh) {
            y[((size_t)bglob*T_ + tt)*YCH + dir*256 + jglob] = hn;
            if (s + 1 < T_) {
                int tn = dir ? (T_-2-s) : (s+1);
                size_t xrow = ((size_t)bglob*T_ + tn) * X3;
                xz = __ldg(&xp[xrow +       jglob]);
                xr = __ldg(&xp[xrow + 256 + jglob]);
                xh = __ldg(&xp[xrow + 512 + jglob]);
            }
        }

        mbar_wait_parity(mbar, (uint32_t)(s & 1));
        p ^= 1;
    }

    if (kh == 0) {
        if (layer == 2)
            hcat[(size_t)bglob*YCH + dir*256 + jglob] = hn;
        else
            g_h[dir][bglob][jglob] = hn;
    }
    CLUSTER_ARRIVE_();   // keep smem alive until all peers' final pushes land
    CLUSTER_WAIT_();
}

// ---------------------------------------------------------------------------
// launch
// ---------------------------------------------------------------------------
extern "C" void kernel_launch(void* const* d_in, const int* in_sizes, int n_in,
                              void* d_out, int out_size)
{
    (void)in_sizes; (void)n_in; (void)out_size;
    const float* x = (const float*)d_in[0];
    const float* p[18];
    for (int i = 0; i < 18; i++) p[i] = (const float*)d_in[1 + i];
    // layer l: fwk=p[6l], fwr=p[6l+1], fwb=p[6l+2], bwk=p[6l+3], bwr=p[6l+4], bwb=p[6l+5]

    float* y    = (float*)d_out;                    // [B][T][512], inter-layer reuse
    float* hcat = y + (size_t)B_ * T_ * YCH;        // [B][512] final states

    cudaFuncSetAttribute(rec_kernel,
                         cudaFuncAttributeMaxDynamicSharedMemorySize,
                         REC_SMEM_BYTES);

    const int tot4 = B_*T_*X3/4;
    layer0_xp_kernel<<<(tot4 + 255)/256, 256>>>(x, p[0], p[2], p[3], p[5]);
    rec_kernel<<<128, REC_THREADS, REC_SMEM_BYTES>>>(p[1], p[2], p[4], p[5], y, hcat, 0);

    dim3 gg(X3/128, (B_*T_)/128, 2);
    gemm_xp_mma_kernel<<<gg, 256>>>(y, p[6], p[8], p[9], p[11]);
    rec_kernel<<<128, REC_THREADS, REC_SMEM_BYTES>>>(p[7], p[8], p[10], p[11], y, hcat, 1);

    gemm_xp_mma_kernel<<<gg, 256>>>(y, p[12], p[14], p[15], p[17]);
    rec_kernel<<<128, REC_THREADS, REC_SMEM_BYTES>>>(p[13], p[14], p[16], p[17], y, hcat, 2);
}